// round 1
// baseline (speedup 1.0000x reference)
#include <cuda_runtime.h>
#include <cuda_bf16.h>
#include <math.h>

#define HID 512
#define BATCH 256
#define TSEQ 600
#define VOCAB 83
#define EMBED 50

// -------- scratch (no allocations allowed) --------
__device__ float g_hidden_attn[BATCH * HID];          // 512 KB
__device__ float g_scores_part[4][BATCH * TSEQ];      // 4 x 600 KB
__device__ float g_context[BATCH * HID];              // 512 KB

__device__ __forceinline__ float tanh_fast(float x) {
    float y;
    asm("tanh.approx.f32 %0, %1;" : "=f"(y) : "f"(x));
    return y;
}
__device__ __forceinline__ float sigmoidf_(float x) {
    return 1.0f / (1.0f + __expf(-x));
}

// ============ K_A: hidden_attn = hidden @ W_hp + b_hp  (256x512x512) ============
__global__ __launch_bounds__(256) void k_hidden_attn(
    const float* __restrict__ hidden, const float* __restrict__ W_hp,
    const float* __restrict__ b_hp) {
    int b = blockIdx.x, tid = threadIdx.x;
    __shared__ float sh[HID];
    sh[tid] = hidden[b * HID + tid];
    sh[tid + 256] = hidden[b * HID + tid + 256];
    __syncthreads();
    #pragma unroll
    for (int jj = 0; jj < 2; jj++) {
        int n = tid + jj * 256;
        float acc = b_hp[n];
        #pragma unroll 8
        for (int k = 0; k < HID; k++) acc += sh[k] * W_hp[k * HID + n];
        g_hidden_attn[b * HID + n] = acc;
    }
}

// ============ K_B: fused enc@W_ep + tanh + dot(w_v) -> score partials ============
// A = encoder_output viewed as (T*B, 512) row-major (row r: t=r>>8, b=r&255)
// grid (1200, 4), 256 threads, 128x128 tile, 8x8 microtile
__global__ __launch_bounds__(256) void k_attn_gemm(
    const float* __restrict__ enc, const float* __restrict__ W_ep,
    const float* __restrict__ b_ep, const float* __restrict__ w_v) {
    __shared__ float As[8][128];
    __shared__ float Bs[8][128];
    __shared__ float spart[128][17];  // [row][tx] partial scores (pad vs conflicts)

    const int row0 = blockIdx.x * 128;
    const int n0   = blockIdx.y * 128;
    const int tid  = threadIdx.x;
    const int tx   = tid & 15;       // col group
    const int ty   = tid >> 4;       // row group

    float acc[8][8];
    #pragma unroll
    for (int i = 0; i < 8; i++)
        #pragma unroll
        for (int j = 0; j < 8; j++) acc[i][j] = 0.f;

    const int arow = tid >> 1;           // 0..127
    const int aseg = (tid & 1) * 4;      // 0 or 4
    const int bk   = tid >> 5;           // 0..7
    const int bn   = (tid & 31) * 4;     // 0..124

    const float* Aptr = enc + (size_t)row0 * HID;

    for (int k0 = 0; k0 < HID; k0 += 8) {
        float4 av = *(const float4*)(Aptr + arow * HID + k0 + aseg);
        float4 bv = *(const float4*)(W_ep + (size_t)(k0 + bk) * HID + n0 + bn);
        As[aseg + 0][arow] = av.x;
        As[aseg + 1][arow] = av.y;
        As[aseg + 2][arow] = av.z;
        As[aseg + 3][arow] = av.w;
        *(float4*)&Bs[bk][bn] = bv;
        __syncthreads();
        #pragma unroll
        for (int k = 0; k < 8; k++) {
            float a[8], bb[8];
            float4 a0 = *(const float4*)&As[k][ty * 8];
            float4 a1 = *(const float4*)&As[k][ty * 8 + 4];
            float4 b0 = *(const float4*)&Bs[k][tx * 8];
            float4 b1 = *(const float4*)&Bs[k][tx * 8 + 4];
            a[0]=a0.x;a[1]=a0.y;a[2]=a0.z;a[3]=a0.w;a[4]=a1.x;a[5]=a1.y;a[6]=a1.z;a[7]=a1.w;
            bb[0]=b0.x;bb[1]=b0.y;bb[2]=b0.z;bb[3]=b0.w;bb[4]=b1.x;bb[5]=b1.y;bb[6]=b1.z;bb[7]=b1.w;
            #pragma unroll
            for (int i = 0; i < 8; i++)
                #pragma unroll
                for (int j = 0; j < 8; j++) acc[i][j] += a[i] * bb[j];
        }
        __syncthreads();
    }

    // epilogue: v = tanh(acc + b_ep + hidden_attn[b]);  partial score += v * w_v
    #pragma unroll
    for (int i = 0; i < 8; i++) {
        int r = row0 + ty * 8 + i;
        int b = r & 255;
        const float* hid = g_hidden_attn + b * HID + n0 + tx * 8;
        float pi = 0.f;
        #pragma unroll
        for (int j = 0; j < 8; j++) {
            int gn = n0 + tx * 8 + j;
            float v = acc[i][j] + b_ep[gn] + hid[j];
            pi += tanh_fast(v) * w_v[gn];
        }
        spart[ty * 8 + i][tx] = pi;
    }
    __syncthreads();
    if (tid < 128) {
        int r = row0 + tid;
        float s = 0.f;
        #pragma unroll
        for (int j = 0; j < 16; j++) s += spart[tid][j];  // fixed order: deterministic
        int b = r & 255, t = r >> 8;
        g_scores_part[blockIdx.y][b * TSEQ + t] = s;
    }
}

// ============ K_C: softmax over t + context = sum_t enc[t,b,:] * w[t] ============
__global__ __launch_bounds__(256) void k_softmax_ctx(
    const float* __restrict__ enc, float* __restrict__ out_attn) {
    int b = blockIdx.x, tid = threadIdx.x;
    __shared__ float sw[TSEQ];
    __shared__ float red[256];

    float lm = -1e30f;
    for (int t = tid; t < TSEQ; t += 256) {
        float s = g_scores_part[0][b * TSEQ + t] + g_scores_part[1][b * TSEQ + t]
                + g_scores_part[2][b * TSEQ + t] + g_scores_part[3][b * TSEQ + t];
        sw[t] = s;
        lm = fmaxf(lm, s);
    }
    red[tid] = lm;
    __syncthreads();
    for (int off = 128; off > 0; off >>= 1) {
        if (tid < off) red[tid] = fmaxf(red[tid], red[tid + off]);
        __syncthreads();
    }
    float m = red[0];
    __syncthreads();
    float ls = 0.f;
    for (int t = tid; t < TSEQ; t += 256) {
        float e = __expf(sw[t] - m);
        sw[t] = e;
        ls += e;
    }
    red[tid] = ls;
    __syncthreads();
    for (int off = 128; off > 0; off >>= 1) {
        if (tid < off) red[tid] += red[tid + off];
        __syncthreads();
    }
    float inv = 1.f / red[0];
    __syncthreads();
    for (int t = tid; t < TSEQ; t += 256) {
        float w = sw[t] * inv;
        sw[t] = w;
        out_attn[b * TSEQ + t] = w;
    }
    __syncthreads();

    // context: h = tid and tid+256, unrolled t for MLP
    float acc0 = 0.f, acc1 = 0.f;
    const float* ep = enc + b * HID + tid;
    #pragma unroll 4
    for (int t = 0; t < TSEQ; t++) {
        float w = sw[t];
        acc0 += ep[(size_t)t * (BATCH * HID)] * w;
        acc1 += ep[(size_t)t * (BATCH * HID) + 256] * w;
    }
    g_context[b * HID + tid] = acc0;
    g_context[b * HID + tid + 256] = acc1;
}

// ============ K_D: GRU cell + output softmax (one block per batch elem) ============
__global__ __launch_bounds__(256) void k_decoder(
    const float* __restrict__ in_char, const float* __restrict__ hidden,
    const float* __restrict__ W_cs, const float* __restrict__ b_cs,
    const float* __restrict__ emb,
    const float* __restrict__ W_ih, const float* __restrict__ b_ih,
    const float* __restrict__ W_hh, const float* __restrict__ b_hh,
    const float* __restrict__ W_out, const float* __restrict__ b_out,
    float* __restrict__ out_logits, float* __restrict__ out_newh) {
    int b = blockIdx.x, tid = threadIdx.x;
    __shared__ float sh[HID], sctx[HID], sdec[6 * EMBED];
    __shared__ float sgi[3 * HID], sgh[3 * HID], snh[HID];
    __shared__ float slog[VOCAB], sexp[VOCAB], sred[2];
    __shared__ int stop1;

    sh[tid] = hidden[b * HID + tid];
    sh[tid + 256] = hidden[b * HID + tid + 256];
    sctx[tid] = g_context[b * HID + tid];
    sctx[tid + 256] = g_context[b * HID + tid + 256];
    if (tid == 0) {
        float bm = in_char[b * VOCAB];
        int bi = 0;
        for (int i = 1; i < VOCAB; i++) {
            float v = in_char[b * VOCAB + i];
            if (v > bm) { bm = v; bi = i; }
        }
        stop1 = bi;
    }
    __syncthreads();

    if (tid < EMBED) sdec[tid] = emb[stop1 * EMBED + tid];
    if (tid < 5 * EMBED) {
        float acc = b_cs[tid];
        #pragma unroll 4
        for (int k = 0; k < HID; k++) acc += sctx[k] * W_cs[k * (5 * EMBED) + tid];
        sdec[EMBED + tid] = acc;
    }
    __syncthreads();

    #pragma unroll
    for (int j = 0; j < 6; j++) {
        int n = tid + j * 256;
        float ai = b_ih[n];
        float ah = b_hh[n];
        #pragma unroll 4
        for (int k = 0; k < 6 * EMBED; k++) ai += sdec[k] * W_ih[k * (3 * HID) + n];
        #pragma unroll 4
        for (int k = 0; k < HID; k++) ah += sh[k] * W_hh[k * (3 * HID) + n];
        sgi[n] = ai;
        sgh[n] = ah;
    }
    __syncthreads();

    #pragma unroll
    for (int jj = 0; jj < 2; jj++) {
        int j = tid + jj * 256;
        float r = sigmoidf_(sgi[j] + sgh[j]);
        float z = sigmoidf_(sgi[HID + j] + sgh[HID + j]);
        float nn = tanhf(sgi[2 * HID + j] + r * sgh[2 * HID + j]);
        float nh = (1.f - z) * nn + z * sh[j];
        snh[j] = nh;
        out_newh[b * HID + j] = nh;
    }
    __syncthreads();

    if (tid < VOCAB) {
        float acc = b_out[tid];
        #pragma unroll 4
        for (int k = 0; k < HID; k++) acc += snh[k] * W_out[k * VOCAB + tid];
        slog[tid] = acc;
    }
    __syncthreads();
    if (tid == 0) {
        float m = slog[0];
        for (int i = 1; i < VOCAB; i++) m = fmaxf(m, slog[i]);
        sred[0] = m;
    }
    __syncthreads();
    if (tid < VOCAB) sexp[tid] = __expf(slog[tid] - sred[0]);
    __syncthreads();
    if (tid == 0) {
        float s = 0.f;
        for (int i = 0; i < VOCAB; i++) s += sexp[i];
        sred[1] = 1.f / s;
    }
    __syncthreads();
    if (tid < VOCAB) out_logits[b * VOCAB + tid] = sexp[tid] * sred[1];
}

// =============================== launcher ===============================
extern "C" void kernel_launch(void* const* d_in, const int* in_sizes, int n_in,
                              void* d_out, int out_size) {
    const float* in_char = (const float*)d_in[0];
    const float* hidden  = (const float*)d_in[1];
    const float* enc     = (const float*)d_in[2];
    const float* W_hp    = (const float*)d_in[3];
    const float* b_hp    = (const float*)d_in[4];
    const float* W_ep    = (const float*)d_in[5];
    const float* b_ep    = (const float*)d_in[6];
    const float* w_v     = (const float*)d_in[7];
    // d_in[8] = b_v: constant shift, cancels in softmax
    const float* W_cs    = (const float*)d_in[9];
    const float* b_cs    = (const float*)d_in[10];
    const float* emb     = (const float*)d_in[11];
    const float* W_ih    = (const float*)d_in[12];
    const float* b_ih    = (const float*)d_in[13];
    const float* W_hh    = (const float*)d_in[14];
    const float* b_hh    = (const float*)d_in[15];
    const float* W_out   = (const float*)d_in[16];
    const float* b_out   = (const float*)d_in[17];

    float* out = (float*)d_out;
    float* out_logits = out;                                // (256, 83)
    float* out_newh   = out + BATCH * VOCAB;                // (1, 256, 512)
    float* out_attn   = out + BATCH * VOCAB + BATCH * HID;  // (256, 600)

    k_hidden_attn<<<BATCH, 256>>>(hidden, W_hp, b_hp);
    k_attn_gemm<<<dim3((TSEQ * BATCH) / 128, 4), 256>>>(enc, W_ep, b_ep, w_v);
    k_softmax_ctx<<<BATCH, 256>>>(enc, out_attn);
    k_decoder<<<BATCH, 256>>>(in_char, hidden, W_cs, b_cs, emb, W_ih, b_ih,
                              W_hh, b_hh, W_out, b_out, out_logits, out_newh);
}

// round 2
// speedup vs baseline: 1.1554x; 1.1554x over previous
#include <cuda_runtime.h>
#include <cuda_bf16.h>
#include <math.h>

#define HID 512
#define BATCH 256
#define TSEQ 600
#define VOCAB 83
#define EMBED 50
#define INDEC_LD 304   // 300 rounded to 8, 16B-aligned rows

// -------- scratch (no allocations allowed) --------
__device__ float g_hidden_attn[BATCH * HID];
__device__ float g_scores_part[4][BATCH * TSEQ];
__device__ float g_context[BATCH * HID];
__device__ float g_indec[BATCH * INDEC_LD];
__device__ float g_gi[BATCH * 3 * HID];
__device__ float g_gh[BATCH * 3 * HID];
__device__ int   g_top1[BATCH];

__device__ __forceinline__ float tanh_fast(float x) {
    float y;
    asm("tanh.approx.f32 %0, %1;" : "=f"(y) : "f"(x));
    return y;
}
__device__ __forceinline__ float sigmoidf_(float x) {
    return 1.0f / (1.0f + __expf(-x));
}

// ============ K_A: hidden_attn = hidden @ W_hp + b_hp  (256x512x512) ============
__global__ __launch_bounds__(256) void k_hidden_attn(
    const float* __restrict__ hidden, const float* __restrict__ W_hp,
    const float* __restrict__ b_hp) {
    int b = blockIdx.x, tid = threadIdx.x;
    __shared__ float sh[HID];
    sh[tid] = hidden[b * HID + tid];
    sh[tid + 256] = hidden[b * HID + tid + 256];
    __syncthreads();
    #pragma unroll
    for (int jj = 0; jj < 2; jj++) {
        int n = tid + jj * 256;
        float acc = b_hp[n];
        #pragma unroll 8
        for (int k = 0; k < HID; k++) acc += sh[k] * W_hp[k * HID + n];
        g_hidden_attn[b * HID + n] = acc;
    }
}

// ============ K_B: fused enc@W_ep + tanh + dot(w_v) -> score partials ============
__global__ __launch_bounds__(256) void k_attn_gemm(
    const float* __restrict__ enc, const float* __restrict__ W_ep,
    const float* __restrict__ b_ep, const float* __restrict__ w_v) {
    __shared__ float As[8][128];
    __shared__ float Bs[8][128];
    __shared__ float spart[128][17];

    const int row0 = blockIdx.x * 128;
    const int n0   = blockIdx.y * 128;
    const int tid  = threadIdx.x;
    const int tx   = tid & 15;
    const int ty   = tid >> 4;

    float acc[8][8];
    #pragma unroll
    for (int i = 0; i < 8; i++)
        #pragma unroll
        for (int j = 0; j < 8; j++) acc[i][j] = 0.f;

    const int arow = tid >> 1;
    const int aseg = (tid & 1) * 4;
    const int bk   = tid >> 5;
    const int bn   = (tid & 31) * 4;

    const float* Aptr = enc + (size_t)row0 * HID;

    for (int k0 = 0; k0 < HID; k0 += 8) {
        float4 av = *(const float4*)(Aptr + arow * HID + k0 + aseg);
        float4 bv = *(const float4*)(W_ep + (size_t)(k0 + bk) * HID + n0 + bn);
        As[aseg + 0][arow] = av.x;
        As[aseg + 1][arow] = av.y;
        As[aseg + 2][arow] = av.z;
        As[aseg + 3][arow] = av.w;
        *(float4*)&Bs[bk][bn] = bv;
        __syncthreads();
        #pragma unroll
        for (int k = 0; k < 8; k++) {
            float a[8], bb[8];
            float4 a0 = *(const float4*)&As[k][ty * 8];
            float4 a1 = *(const float4*)&As[k][ty * 8 + 4];
            float4 b0 = *(const float4*)&Bs[k][tx * 8];
            float4 b1 = *(const float4*)&Bs[k][tx * 8 + 4];
            a[0]=a0.x;a[1]=a0.y;a[2]=a0.z;a[3]=a0.w;a[4]=a1.x;a[5]=a1.y;a[6]=a1.z;a[7]=a1.w;
            bb[0]=b0.x;bb[1]=b0.y;bb[2]=b0.z;bb[3]=b0.w;bb[4]=b1.x;bb[5]=b1.y;bb[6]=b1.z;bb[7]=b1.w;
            #pragma unroll
            for (int i = 0; i < 8; i++)
                #pragma unroll
                for (int j = 0; j < 8; j++) acc[i][j] += a[i] * bb[j];
        }
        __syncthreads();
    }

    #pragma unroll
    for (int i = 0; i < 8; i++) {
        int r = row0 + ty * 8 + i;
        int b = r & 255;
        const float* hid = g_hidden_attn + b * HID + n0 + tx * 8;
        float pi = 0.f;
        #pragma unroll
        for (int j = 0; j < 8; j++) {
            int gn = n0 + tx * 8 + j;
            float v = acc[i][j] + b_ep[gn] + hid[j];
            pi += tanh_fast(v) * w_v[gn];
        }
        spart[ty * 8 + i][tx] = pi;
    }
    __syncthreads();
    if (tid < 128) {
        int r = row0 + tid;
        float s = 0.f;
        #pragma unroll
        for (int j = 0; j < 16; j++) s += spart[tid][j];
        int b = r & 255, t = r >> 8;
        g_scores_part[blockIdx.y][b * TSEQ + t] = s;
    }
}

// ============ K_C: softmax over t + context ============
__global__ __launch_bounds__(256) void k_softmax_ctx(
    const float* __restrict__ enc, float* __restrict__ out_attn) {
    int b = blockIdx.x, tid = threadIdx.x;
    __shared__ float sw[TSEQ];
    __shared__ float red[256];

    float lm = -1e30f;
    for (int t = tid; t < TSEQ; t += 256) {
        float s = g_scores_part[0][b * TSEQ + t] + g_scores_part[1][b * TSEQ + t]
                + g_scores_part[2][b * TSEQ + t] + g_scores_part[3][b * TSEQ + t];
        sw[t] = s;
        lm = fmaxf(lm, s);
    }
    red[tid] = lm;
    __syncthreads();
    for (int off = 128; off > 0; off >>= 1) {
        if (tid < off) red[tid] = fmaxf(red[tid], red[tid + off]);
        __syncthreads();
    }
    float m = red[0];
    __syncthreads();
    float ls = 0.f;
    for (int t = tid; t < TSEQ; t += 256) {
        float e = __expf(sw[t] - m);
        sw[t] = e;
        ls += e;
    }
    red[tid] = ls;
    __syncthreads();
    for (int off = 128; off > 0; off >>= 1) {
        if (tid < off) red[tid] += red[tid + off];
        __syncthreads();
    }
    float inv = 1.f / red[0];
    __syncthreads();
    for (int t = tid; t < TSEQ; t += 256) {
        float w = sw[t] * inv;
        sw[t] = w;
        out_attn[b * TSEQ + t] = w;
    }
    __syncthreads();

    float acc0 = 0.f, acc1 = 0.f;
    const float* ep = enc + b * HID + tid;
    #pragma unroll 4
    for (int t = 0; t < TSEQ; t++) {
        float w = sw[t];
        acc0 += ep[(size_t)t * (BATCH * HID)] * w;
        acc1 += ep[(size_t)t * (BATCH * HID) + 256] * w;
    }
    g_context[b * HID + tid] = acc0;
    g_context[b * HID + tid + 256] = acc1;
}

// ============ argmax + embedding gather + pad (grid=BATCH, block=64) ============
__global__ __launch_bounds__(64) void k_argmax_embed(
    const float* __restrict__ in_char, const float* __restrict__ emb) {
    int b = blockIdx.x, tid = threadIdx.x;
    __shared__ int s_idx;
    if (tid < 32) {
        float bv = -1e30f; int bi = 0;
        for (int i = tid; i < VOCAB; i += 32) {
            float v = in_char[b * VOCAB + i];
            if (v > bv) { bv = v; bi = i; }
        }
        #pragma unroll
        for (int off = 16; off > 0; off >>= 1) {
            float ov = __shfl_down_sync(0xffffffffu, bv, off);
            int   oi = __shfl_down_sync(0xffffffffu, bi, off);
            if (ov > bv || (ov == bv && oi < bi)) { bv = ov; bi = oi; }
        }
        if (tid == 0) { s_idx = bi; g_top1[b] = bi; }
    }
    __syncthreads();
    int t1 = s_idx;
    if (tid < EMBED) g_indec[b * INDEC_LD + tid] = emb[t1 * EMBED + tid];
    if (tid >= EMBED && tid < EMBED + 4)  // zero K-pad cols 300..303
        g_indec[b * INDEC_LD + 300 + (tid - EMBED)] = 0.f;
}

// ============ generic bounds-checked tiled GEMM: C = A@B + bias ============
// 128x128 tile, 256 threads, 8x8 micro. M multiple of 128 (grid.x covers it).
// A row-major (lda >= Kpad, rows zero-padded to Kpad). B row-major (ldb = N real).
__global__ __launch_bounds__(256) void k_gemm_tail(
    const float* __restrict__ A, int lda,
    const float* __restrict__ B, int ldb,
    const float* __restrict__ bias,
    float* __restrict__ C, int ldc, int N, int K) {
    __shared__ float As[8][128];
    __shared__ float Bs[8][128];

    const int row0 = blockIdx.x * 128;
    const int n0   = blockIdx.y * 128;
    const int tid  = threadIdx.x;
    const int tx   = tid & 15;
    const int ty   = tid >> 4;

    float acc[8][8];
    #pragma unroll
    for (int i = 0; i < 8; i++)
        #pragma unroll
        for (int j = 0; j < 8; j++) acc[i][j] = 0.f;

    const int arow = tid >> 1;
    const int aseg = (tid & 1) * 4;
    const int Kpad = (K + 7) & ~7;

    for (int k0 = 0; k0 < Kpad; k0 += 8) {
        float4 av = *(const float4*)(A + (size_t)(row0 + arow) * lda + k0 + aseg);
        As[aseg + 0][arow] = av.x;
        As[aseg + 1][arow] = av.y;
        As[aseg + 2][arow] = av.z;
        As[aseg + 3][arow] = av.w;
        #pragma unroll
        for (int j = 0; j < 4; j++) {
            int e = tid + j * 256;
            int bk = e >> 7, bn = e & 127;
            int gk = k0 + bk, gn = n0 + bn;
            Bs[bk][bn] = (gk < K && gn < N) ? B[(size_t)gk * ldb + gn] : 0.f;
        }
        __syncthreads();
        #pragma unroll
        for (int k = 0; k < 8; k++) {
            float a[8], bb[8];
            float4 a0 = *(const float4*)&As[k][ty * 8];
            float4 a1 = *(const float4*)&As[k][ty * 8 + 4];
            float4 b0 = *(const float4*)&Bs[k][tx * 8];
            float4 b1 = *(const float4*)&Bs[k][tx * 8 + 4];
            a[0]=a0.x;a[1]=a0.y;a[2]=a0.z;a[3]=a0.w;a[4]=a1.x;a[5]=a1.y;a[6]=a1.z;a[7]=a1.w;
            bb[0]=b0.x;bb[1]=b0.y;bb[2]=b0.z;bb[3]=b0.w;bb[4]=b1.x;bb[5]=b1.y;bb[6]=b1.z;bb[7]=b1.w;
            #pragma unroll
            for (int i = 0; i < 8; i++)
                #pragma unroll
                for (int j = 0; j < 8; j++) acc[i][j] += a[i] * bb[j];
        }
        __syncthreads();
    }

    #pragma unroll
    for (int i = 0; i < 8; i++) {
        int r = row0 + ty * 8 + i;
        #pragma unroll
        for (int j = 0; j < 8; j++) {
            int c = n0 + tx * 8 + j;
            if (c < N) C[(size_t)r * ldc + c] = acc[i][j] + bias[c];
        }
    }
}

// ============ GRU gates elementwise ============
__global__ __launch_bounds__(256) void k_gates(
    const float* __restrict__ hidden, float* __restrict__ out_newh) {
    int idx = blockIdx.x * 256 + threadIdx.x;   // 0 .. 256*512-1
    int b = idx >> 9, j = idx & 511;
    const float* gi = g_gi + b * 3 * HID;
    const float* gh = g_gh + b * 3 * HID;
    float r = sigmoidf_(gi[j] + gh[j]);
    float z = sigmoidf_(gi[HID + j] + gh[HID + j]);
    float n = tanhf(gi[2 * HID + j] + r * gh[2 * HID + j]);
    float h = hidden[idx];
    out_newh[idx] = (1.f - z) * n + z * h;
}

// ============ output logits + softmax (grid=BATCH, block=128) ============
__global__ __launch_bounds__(128) void k_out_softmax(
    const float* __restrict__ newh, const float* __restrict__ W_out,
    const float* __restrict__ b_out, float* __restrict__ out_logits) {
    int b = blockIdx.x, tid = threadIdx.x;
    __shared__ float sh[HID];
    __shared__ float se[VOCAB];
    __shared__ float sred[2];
    #pragma unroll
    for (int i = 0; i < 4; i++) sh[tid + i * 128] = newh[b * HID + tid + i * 128];
    __syncthreads();
    if (tid < VOCAB) {
        float acc = b_out[tid];
        #pragma unroll 8
        for (int k = 0; k < HID; k++) acc += sh[k] * W_out[k * VOCAB + tid];
        se[tid] = acc;
    }
    __syncthreads();
    if (tid == 0) {
        float m = se[0];
        for (int i = 1; i < VOCAB; i++) m = fmaxf(m, se[i]);
        sred[0] = m;
    }
    __syncthreads();
    if (tid < VOCAB) se[tid] = __expf(se[tid] - sred[0]);
    __syncthreads();
    if (tid == 0) {
        float s = 0.f;
        for (int i = 0; i < VOCAB; i++) s += se[i];
        sred[1] = 1.f / s;
    }
    __syncthreads();
    if (tid < VOCAB) out_logits[b * VOCAB + tid] = se[tid] * sred[1];
}

// =============================== launcher ===============================
extern "C" void kernel_launch(void* const* d_in, const int* in_sizes, int n_in,
                              void* d_out, int out_size) {
    const float* in_char = (const float*)d_in[0];
    const float* hidden  = (const float*)d_in[1];
    const float* enc     = (const float*)d_in[2];
    const float* W_hp    = (const float*)d_in[3];
    const float* b_hp    = (const float*)d_in[4];
    const float* W_ep    = (const float*)d_in[5];
    const float* b_ep    = (const float*)d_in[6];
    const float* w_v     = (const float*)d_in[7];
    // d_in[8] = b_v: constant shift, cancels in softmax
    const float* W_cs    = (const float*)d_in[9];
    const float* b_cs    = (const float*)d_in[10];
    const float* emb     = (const float*)d_in[11];
    const float* W_ih    = (const float*)d_in[12];
    const float* b_ih    = (const float*)d_in[13];
    const float* W_hh    = (const float*)d_in[14];
    const float* b_hh    = (const float*)d_in[15];
    const float* W_out   = (const float*)d_in[16];
    const float* b_out   = (const float*)d_in[17];

    float* out = (float*)d_out;
    float* out_logits = out;
    float* out_newh   = out + BATCH * VOCAB;
    float* out_attn   = out + BATCH * VOCAB + BATCH * HID;

    float* p_indec; cudaGetSymbolAddress((void**)&p_indec, g_indec);
    float* p_gi;    cudaGetSymbolAddress((void**)&p_gi, g_gi);
    float* p_gh;    cudaGetSymbolAddress((void**)&p_gh, g_gh);
    float* p_ctx;   cudaGetSymbolAddress((void**)&p_ctx, g_context);

    // attention path
    k_hidden_attn<<<BATCH, 256>>>(hidden, W_hp, b_hp);
    k_attn_gemm<<<dim3((TSEQ * BATCH) / 128, 4), 256>>>(enc, W_ep, b_ep, w_v);
    k_softmax_ctx<<<BATCH, 256>>>(enc, out_attn);

    // decoder tail as batched GEMMs
    k_argmax_embed<<<BATCH, 64>>>(in_char, emb);
    // in_dec[:, 50:300] = context @ W_cs + b_cs   (M=256, N=250, K=512)
    k_gemm_tail<<<dim3(2, 2), 256>>>(p_ctx, HID, W_cs, 250, b_cs,
                                     p_indec + EMBED, INDEC_LD, 250, HID);
    // gi = in_dec @ W_ih + b_ih   (M=256, N=1536, K=300)
    k_gemm_tail<<<dim3(2, 12), 256>>>(p_indec, INDEC_LD, W_ih, 3 * HID, b_ih,
                                      p_gi, 3 * HID, 3 * HID, 300);
    // gh = h @ W_hh + b_hh        (M=256, N=1536, K=512)
    k_gemm_tail<<<dim3(2, 12), 256>>>(hidden, HID, W_hh, 3 * HID, b_hh,
                                      p_gh, 3 * HID, 3 * HID, HID);
    k_gates<<<(BATCH * HID) / 256, 256>>>(hidden, out_newh);
    k_out_softmax<<<BATCH, 128>>>(out_newh, W_out, b_out, out_logits);
}

// round 4
// speedup vs baseline: 2.6097x; 2.2587x over previous
#include <cuda_runtime.h>
#include <math.h>
#include <cstdint>

#define HID 512
#define BATCH 256
#define TSEQ 600
#define VOCAB 83
#define EMBED 50
#define INDEC_LD 304

// -------- scratch --------
__device__ float g_hidden_attn[BATCH * HID];
__device__ float g_scores_part[8][BATCH * TSEQ];
__device__ float g_context[BATCH * HID];
__device__ float g_indec[BATCH * INDEC_LD];
__device__ float g_gi[BATCH * 3 * HID];
__device__ float g_gh[BATCH * 3 * HID];
__device__ float g_Wep_T[HID * HID];   // [n][k], tf32-rounded

__device__ __forceinline__ float tanh_fast(float x) {
    float y; asm("tanh.approx.f32 %0, %1;" : "=f"(y) : "f"(x)); return y;
}
__device__ __forceinline__ float sigmoidf_(float x) {
    return 1.0f / (1.0f + __expf(-x));
}
__device__ __forceinline__ float to_tf32(float x) {
    float y; asm("cvt.rna.tf32.f32 %0, %1;" : "=f"(y) : "f"(x)); return y;
}
__device__ __forceinline__ void mma_tf32(float* c, const uint32_t* a, const uint32_t* b) {
    asm volatile(
        "mma.sync.aligned.m16n8k8.row.col.f32.tf32.tf32.f32 "
        "{%0,%1,%2,%3}, {%4,%5,%6,%7}, {%8,%9}, {%0,%1,%2,%3};"
        : "+f"(c[0]), "+f"(c[1]), "+f"(c[2]), "+f"(c[3])
        : "r"(a[0]), "r"(a[1]), "r"(a[2]), "r"(a[3]), "r"(b[0]), "r"(b[1]));
}

// ===== transpose + tf32-round W_ep: g_Wep_T[n][k] = rna(W_ep[k][n]) =====
__global__ __launch_bounds__(256) void k_transpose_wep(const float* __restrict__ W) {
    __shared__ float t[32][33];
    int bx = blockIdx.x * 32, by = blockIdx.y * 32;
    int x = threadIdx.x & 31, y = threadIdx.x >> 5;
    #pragma unroll
    for (int i = 0; i < 32; i += 8)
        t[y + i][x] = to_tf32(W[(size_t)(by + y + i) * HID + bx + x]);
    __syncthreads();
    #pragma unroll
    for (int i = 0; i < 32; i += 8)
        g_Wep_T[(size_t)(bx + y + i) * HID + by + x] = t[x][y + i];
}

// ===== K_A: hidden_attn = hidden @ W_hp + b_hp =====
__global__ __launch_bounds__(256) void k_hidden_attn(
    const float* __restrict__ hidden, const float* __restrict__ W_hp,
    const float* __restrict__ b_hp) {
    int b = blockIdx.x, tid = threadIdx.x;
    __shared__ float sh[HID];
    sh[tid] = hidden[b * HID + tid];
    sh[tid + 256] = hidden[b * HID + tid + 256];
    __syncthreads();
    #pragma unroll
    for (int jj = 0; jj < 2; jj++) {
        int n = tid + jj * 256;
        float acc = b_hp[n];
        #pragma unroll 8
        for (int k = 0; k < HID; k++) acc += sh[k] * W_hp[k * HID + n];
        g_hidden_attn[b * HID + n] = acc;
    }
}

// ===== K_B: tf32 mma.sync fused GEMM + tanh + dot(w_v) =====
// grid (1200, 4), 256 threads = 8 warps (4 M x 2 N). CTA tile 128x128, warp 32x64.
__global__ __launch_bounds__(256, 2) void k_attn_gemm_mma(
    const float* __restrict__ enc, const float* __restrict__ b_ep,
    const float* __restrict__ w_v) {
    __shared__ float As[128][36];
    __shared__ float Bs[128][36];

    const int tid = threadIdx.x;
    const int lane = tid & 31, wid = tid >> 5;
    const int warp_m = wid & 3, warp_n = wid >> 2;
    const int row0 = blockIdx.x * 128, n0 = blockIdx.y * 128;
    const int qr = lane >> 2, qc = lane & 3;

    float acc[2][8][4];
    #pragma unroll
    for (int m = 0; m < 2; m++)
        #pragma unroll
        for (int j = 0; j < 8; j++)
            #pragma unroll
            for (int i = 0; i < 4; i++) acc[m][j][i] = 0.f;

    const float* Ag = enc + (size_t)row0 * HID;
    const float* Bg = g_Wep_T + (size_t)n0 * HID;

    for (int k0 = 0; k0 < HID; k0 += 32) {
        #pragma unroll
        for (int i = 0; i < 4; i++) {
            int e = tid + i * 256;          // 0..1023
            int r = e >> 3, c = (e & 7) * 4;
            float4 v = *(const float4*)(Ag + (size_t)r * HID + k0 + c);
            v.x = to_tf32(v.x); v.y = to_tf32(v.y);
            v.z = to_tf32(v.z); v.w = to_tf32(v.w);
            *(float4*)&As[r][c] = v;
            float4 w = *(const float4*)(Bg + (size_t)r * HID + k0 + c);
            *(float4*)&Bs[r][c] = w;
        }
        __syncthreads();
        #pragma unroll
        for (int ks = 0; ks < 4; ks++) {
            const int kk = ks * 8;
            uint32_t a[2][4];
            #pragma unroll
            for (int m = 0; m < 2; m++) {
                int br = warp_m * 32 + m * 16 + qr;
                a[m][0] = __float_as_uint(As[br][kk + qc]);
                a[m][1] = __float_as_uint(As[br + 8][kk + qc]);
                a[m][2] = __float_as_uint(As[br][kk + qc + 4]);
                a[m][3] = __float_as_uint(As[br + 8][kk + qc + 4]);
            }
            uint32_t b[8][2];
            #pragma unroll
            for (int j = 0; j < 8; j++) {
                int bn = warp_n * 64 + j * 8 + qr;
                b[j][0] = __float_as_uint(Bs[bn][kk + qc]);
                b[j][1] = __float_as_uint(Bs[bn][kk + qc + 4]);
            }
            #pragma unroll
            for (int m = 0; m < 2; m++)
                #pragma unroll
                for (int j = 0; j < 8; j++)
                    mma_tf32(acc[m][j], a[m], b[j]);
        }
        __syncthreads();
    }

    // hoist per-column b_ep, w_v (16 columns per thread)
    float bep_r[16], wv_r[16];
    #pragma unroll
    for (int j = 0; j < 8; j++) {
        int c = n0 + warp_n * 64 + j * 8 + qc * 2;
        bep_r[j * 2] = b_ep[c];     bep_r[j * 2 + 1] = b_ep[c + 1];
        wv_r[j * 2]  = w_v[c];      wv_r[j * 2 + 1]  = w_v[c + 1];
    }

    // epilogue: 4 row-groups per thread; quad-shfl reduce; deterministic partials
    #pragma unroll
    for (int g = 0; g < 4; g++) {
        int m = g >> 1;
        int lr = warp_m * 32 + m * 16 + (g & 1) * 8 + qr;
        int r = row0 + lr;
        int bb = r & 255;
        const float* hid = g_hidden_attn + (size_t)bb * HID + n0 + warp_n * 64;
        const int i0 = (g & 1) * 2;
        float p = 0.f;
        #pragma unroll
        for (int j = 0; j < 8; j++) {
            int cl = j * 8 + qc * 2;
            float v0 = acc[m][j][i0]     + bep_r[j * 2]     + hid[cl];
            float v1 = acc[m][j][i0 + 1] + bep_r[j * 2 + 1] + hid[cl + 1];
            p += tanh_fast(v0) * wv_r[j * 2] + tanh_fast(v1) * wv_r[j * 2 + 1];
        }
        p += __shfl_xor_sync(0xffffffffu, p, 1);
        p += __shfl_xor_sync(0xffffffffu, p, 2);
        if (qc == 0) {
            int t = r >> 8;
            g_scores_part[blockIdx.y * 2 + warp_n][bb * TSEQ + t] = p;
        }
    }
}

// ===== K_C: softmax over t + context =====
__global__ __launch_bounds__(256) void k_softmax_ctx(
    const float* __restrict__ enc, float* __restrict__ out_attn) {
    int b = blockIdx.x, tid = threadIdx.x;
    __shared__ float sw[TSEQ];
    __shared__ float red[256];

    float lm = -1e30f;
    for (int t = tid; t < TSEQ; t += 256) {
        float s = 0.f;
        #pragma unroll
        for (int q = 0; q < 8; q++) s += g_scores_part[q][b * TSEQ + t];
        sw[t] = s;
        lm = fmaxf(lm, s);
    }
    red[tid] = lm;
    __syncthreads();
    for (int off = 128; off > 0; off >>= 1) {
        if (tid < off) red[tid] = fmaxf(red[tid], red[tid + off]);
        __syncthreads();
    }
    float m = red[0];
    __syncthreads();
    float ls = 0.f;
    for (int t = tid; t < TSEQ; t += 256) {
        float e = __expf(sw[t] - m);
        sw[t] = e;
        ls += e;
    }
    red[tid] = ls;
    __syncthreads();
    for (int off = 128; off > 0; off >>= 1) {
        if (tid < off) red[tid] += red[tid + off];
        __syncthreads();
    }
    float inv = 1.f / red[0];
    __syncthreads();
    for (int t = tid; t < TSEQ; t += 256) {
        float w = sw[t] * inv;
        sw[t] = w;
        out_attn[b * TSEQ + t] = w;
    }
    __syncthreads();

    float acc0 = 0.f, acc1 = 0.f;
    const float* ep = enc + b * HID + tid;
    #pragma unroll 4
    for (int t = 0; t < TSEQ; t++) {
        float w = sw[t];
        acc0 += ep[(size_t)t * (BATCH * HID)] * w;
        acc1 += ep[(size_t)t * (BATCH * HID) + 256] * w;
    }
    g_context[b * HID + tid] = acc0;
    g_context[b * HID + tid + 256] = acc1;
}

// ===== argmax + embed =====
__global__ __launch_bounds__(64) void k_argmax_embed(
    const float* __restrict__ in_char, const float* __restrict__ emb) {
    int b = blockIdx.x, tid = threadIdx.x;
    __shared__ int s_idx;
    if (tid < 32) {
        float bv = -1e30f; int bi = 0;
        for (int i = tid; i < VOCAB; i += 32) {
            float v = in_char[b * VOCAB + i];
            if (v > bv) { bv = v; bi = i; }
        }
        #pragma unroll
        for (int off = 16; off > 0; off >>= 1) {
            float ov = __shfl_down_sync(0xffffffffu, bv, off);
            int   oi = __shfl_down_sync(0xffffffffu, bi, off);
            if (ov > bv || (ov == bv && oi < bi)) { bv = ov; bi = oi; }
        }
        if (tid == 0) s_idx = bi;
    }
    __syncthreads();
    int t1 = s_idx;
    if (tid < EMBED) g_indec[b * INDEC_LD + tid] = emb[t1 * EMBED + tid];
    if (tid >= EMBED && tid < EMBED + 4)
        g_indec[b * INDEC_LD + 300 + (tid - EMBED)] = 0.f;
}

// ===== generic tiled GEMM (tail) =====
__global__ __launch_bounds__(256) void k_gemm_tail(
    const float* __restrict__ A, int lda,
    const float* __restrict__ B, int ldb,
    const float* __restrict__ bias,
    float* __restrict__ C, int ldc, int N, int K) {
    __shared__ float As[8][128];
    __shared__ float Bs[8][128];

    const int row0 = blockIdx.x * 128;
    const int n0   = blockIdx.y * 128;
    const int tid  = threadIdx.x;
    const int tx   = tid & 15;
    const int ty   = tid >> 4;

    float acc[8][8];
    #pragma unroll
    for (int i = 0; i < 8; i++)
        #pragma unroll
        for (int j = 0; j < 8; j++) acc[i][j] = 0.f;

    const int arow = tid >> 1;
    const int aseg = (tid & 1) * 4;
    const int Kpad = (K + 7) & ~7;

    for (int k0 = 0; k0 < Kpad; k0 += 8) {
        float4 av = *(const float4*)(A + (size_t)(row0 + arow) * lda + k0 + aseg);
        As[aseg + 0][arow] = av.x;
        As[aseg + 1][arow] = av.y;
        As[aseg + 2][arow] = av.z;
        As[aseg + 3][arow] = av.w;
        #pragma unroll
        for (int j = 0; j < 4; j++) {
            int e = tid + j * 256;
            int bk = e >> 7, bn = e & 127;
            int gk = k0 + bk, gn = n0 + bn;
            Bs[bk][bn] = (gk < K && gn < N) ? B[(size_t)gk * ldb + gn] : 0.f;
        }
        __syncthreads();
        #pragma unroll
        for (int k = 0; k < 8; k++) {
            float a[8], bb[8];
            float4 a0 = *(const float4*)&As[k][ty * 8];
            float4 a1 = *(const float4*)&As[k][ty * 8 + 4];
            float4 b0 = *(const float4*)&Bs[k][tx * 8];
            float4 b1 = *(const float4*)&Bs[k][tx * 8 + 4];
            a[0]=a0.x;a[1]=a0.y;a[2]=a0.z;a[3]=a0.w;a[4]=a1.x;a[5]=a1.y;a[6]=a1.z;a[7]=a1.w;
            bb[0]=b0.x;bb[1]=b0.y;bb[2]=b0.z;bb[3]=b0.w;bb[4]=b1.x;bb[5]=b1.y;bb[6]=b1.z;bb[7]=b1.w;
            #pragma unroll
            for (int i = 0; i < 8; i++)
                #pragma unroll
                for (int j = 0; j < 8; j++) acc[i][j] += a[i] * bb[j];
        }
        __syncthreads();
    }

    #pragma unroll
    for (int i = 0; i < 8; i++) {
        int r = row0 + ty * 8 + i;
        #pragma unroll
        for (int j = 0; j < 8; j++) {
            int c = n0 + tx * 8 + j;
            if (c < N) C[(size_t)r * ldc + c] = acc[i][j] + bias[c];
        }
    }
}

// ===== GRU gates =====
__global__ __launch_bounds__(256) void k_gates(
    const float* __restrict__ hidden, float* __restrict__ out_newh) {
    int idx = blockIdx.x * 256 + threadIdx.x;
    int b = idx >> 9, j = idx & 511;
    const float* gi = g_gi + b * 3 * HID;
    const float* gh = g_gh + b * 3 * HID;
    float r = sigmoidf_(gi[j] + gh[j]);
    float z = sigmoidf_(gi[HID + j] + gh[HID + j]);
    float n = tanhf(gi[2 * HID + j] + r * gh[2 * HID + j]);
    float h = hidden[idx];
    out_newh[idx] = (1.f - z) * n + z * h;
}

// ===== output softmax =====
__global__ __launch_bounds__(128) void k_out_softmax(
    const float* __restrict__ newh, const float* __restrict__ W_out,
    const float* __restrict__ b_out, float* __restrict__ out_logits) {
    int b = blockIdx.x, tid = threadIdx.x;
    __shared__ float sh[HID];
    __shared__ float se[VOCAB];
    __shared__ float sred[2];
    #pragma unroll
    for (int i = 0; i < 4; i++) sh[tid + i * 128] = newh[b * HID + tid + i * 128];
    __syncthreads();
    if (tid < VOCAB) {
        float acc = b_out[tid];
        #pragma unroll 8
        for (int k = 0; k < HID; k++) acc += sh[k] * W_out[k * VOCAB + tid];
        se[tid] = acc;
    }
    __syncthreads();
    if (tid == 0) {
        float m = se[0];
        for (int i = 1; i < VOCAB; i++) m = fmaxf(m, se[i]);
        sred[0] = m;
    }
    __syncthreads();
    if (tid < VOCAB) se[tid] = __expf(se[tid] - sred[0]);
    __syncthreads();
    if (tid == 0) {
        float s = 0.f;
        for (int i = 0; i < VOCAB; i++) s += se[i];
        sred[1] = 1.f / s;
    }
    __syncthreads();
    if (tid < VOCAB) out_logits[b * VOCAB + tid] = se[tid] * sred[1];
}

// =============================== launcher ===============================
extern "C" void kernel_launch(void* const* d_in, const int* in_sizes, int n_in,
                              void* d_out, int out_size) {
    const float* in_char = (const float*)d_in[0];
    const float* hidden  = (const float*)d_in[1];
    const float* enc     = (const float*)d_in[2];
    const float* W_hp    = (const float*)d_in[3];
    const float* b_hp    = (const float*)d_in[4];
    const float* W_ep    = (const float*)d_in[5];
    const float* b_ep    = (const float*)d_in[6];
    const float* w_v     = (const float*)d_in[7];
    const float* W_cs    = (const float*)d_in[9];
    const float* b_cs    = (const float*)d_in[10];
    const float* emb     = (const float*)d_in[11];
    const float* W_ih    = (const float*)d_in[12];
    const float* b_ih    = (const float*)d_in[13];
    const float* W_hh    = (const float*)d_in[14];
    const float* b_hh    = (const float*)d_in[15];
    const float* W_out   = (const float*)d_in[16];
    const float* b_out   = (const float*)d_in[17];

    float* out = (float*)d_out;
    float* out_logits = out;
    float* out_newh   = out + BATCH * VOCAB;
    float* out_attn   = out + BATCH * VOCAB + BATCH * HID;

    float* p_indec; cudaGetSymbolAddress((void**)&p_indec, g_indec);
    float* p_gi;    cudaGetSymbolAddress((void**)&p_gi, g_gi);
    float* p_gh;    cudaGetSymbolAddress((void**)&p_gh, g_gh);
    float* p_ctx;   cudaGetSymbolAddress((void**)&p_ctx, g_context);

    // attention path
    k_transpose_wep<<<dim3(16, 16), 256>>>(W_ep);
    k_hidden_attn<<<BATCH, 256>>>(hidden, W_hp, b_hp);
    k_attn_gemm_mma<<<dim3((TSEQ * BATCH) / 128, 4), 256>>>(enc, b_ep, w_v);
    k_softmax_ctx<<<BATCH, 256>>>(enc, out_attn);

    // decoder tail
    k_argmax_embed<<<BATCH, 64>>>(in_char, emb);
    k_gemm_tail<<<dim3(2, 2), 256>>>(p_ctx, HID, W_cs, 250, b_cs,
                                     p_indec + EMBED, INDEC_LD, 250, HID);
    k_gemm_tail<<<dim3(2, 12), 256>>>(p_indec, INDEC_LD, W_ih, 3 * HID, b_ih,
                                      p_gi, 3 * HID, 3 * HID, 300);
    k_gemm_tail<<<dim3(2, 12), 256>>>(hidden, HID, W_hh, 3 * HID, b_hh,
                                      p_gh, 3 * HID, 3 * HID, HID);
    k_gates<<<(BATCH * HID) / 256, 256>>>(hidden, out_newh);
    k_out_softmax<<<BATCH, 128>>>(out_newh, W_out, b_out, out_logits);
}

// round 7
// speedup vs baseline: 2.7789x; 1.0648x over previous
#include <cuda_runtime.h>
#include <math.h>
#include <cstdint>

#define HID 512
#define BATCH 256
#define TSEQ 600
#define VOCAB 83
#define EMBED 50
#define INDEC_LD 304
#define TCHUNK 150

// -------- scratch --------
__device__ float g_hidden_attn[BATCH * HID];
__device__ float g_scores_part[8][BATCH * TSEQ];
__device__ float g_context[BATCH * HID];
__device__ float g_ctx_part[4][BATCH * HID];
__device__ float g_indec[BATCH * INDEC_LD];
__device__ float g_gi[BATCH * 3 * HID];
__device__ float g_gh[BATCH * 3 * HID];
__device__ float g_Wep_T[HID * HID];   // [n][k], tf32-rounded

__device__ __forceinline__ float tanh_fast(float x) {
    float y; asm("tanh.approx.f32 %0, %1;" : "=f"(y) : "f"(x)); return y;
}
__device__ __forceinline__ float sigmoidf_(float x) {
    return 1.0f / (1.0f + __expf(-x));
}
__device__ __forceinline__ float to_tf32(float x) {
    float y; asm("cvt.rna.tf32.f32 %0, %1;" : "=f"(y) : "f"(x)); return y;
}
__device__ __forceinline__ void mma_tf32(float* c, const uint32_t* a, const uint32_t* b) {
    asm volatile(
        "mma.sync.aligned.m16n8k8.row.col.f32.tf32.tf32.f32 "
        "{%0,%1,%2,%3}, {%4,%5,%6,%7}, {%8,%9}, {%0,%1,%2,%3};"
        : "+f"(c[0]), "+f"(c[1]), "+f"(c[2]), "+f"(c[3])
        : "r"(a[0]), "r"(a[1]), "r"(a[2]), "r"(a[3]), "r"(b[0]), "r"(b[1]));
}
__device__ __forceinline__ void cp_async16(uint32_t dst, const void* src) {
    asm volatile("cp.async.cg.shared.global [%0], [%1], 16;" :: "r"(dst), "l"(src));
}
#define CP_COMMIT() asm volatile("cp.async.commit_group;" ::: "memory")
#define CP_WAIT(n)  asm volatile("cp.async.wait_group %0;" :: "n"(n) : "memory")

// ===== transpose + tf32-round W_ep: g_Wep_T[n][k] = rna(W_ep[k][n]) =====
__global__ __launch_bounds__(256) void k_transpose_wep(const float* __restrict__ W) {
    __shared__ float t[32][33];
    int bx = blockIdx.x * 32, by = blockIdx.y * 32;
    int x = threadIdx.x & 31, y = threadIdx.x >> 5;
    #pragma unroll
    for (int i = 0; i < 32; i += 8)
        t[y + i][x] = to_tf32(W[(size_t)(by + y + i) * HID + bx + x]);
    __syncthreads();
    #pragma unroll
    for (int i = 0; i < 32; i += 8)
        g_Wep_T[(size_t)(bx + y + i) * HID + by + x] = t[x][y + i];
}

// ===== K_A: hidden_attn = hidden @ W_hp + b_hp =====
__global__ __launch_bounds__(256) void k_hidden_attn(
    const float* __restrict__ hidden, const float* __restrict__ W_hp,
    const float* __restrict__ b_hp) {
    int b = blockIdx.x, tid = threadIdx.x;
    __shared__ float sh[HID];
    sh[tid] = hidden[b * HID + tid];
    sh[tid + 256] = hidden[b * HID + tid + 256];
    __syncthreads();
    #pragma unroll
    for (int jj = 0; jj < 2; jj++) {
        int n = tid + jj * 256;
        float acc = b_hp[n];
        #pragma unroll 8
        for (int k = 0; k < HID; k++) acc += sh[k] * W_hp[k * HID + n];
        g_hidden_attn[b * HID + n] = acc;
    }
}

// ===== K_B: tf32 mma.sync fused GEMM, cp.async double-buffered =====
// grid (1200, 2), 512 threads = 16 warps (4 M x 4 N). CTA tile 128x256, warp 32x64.
#define A_STRIDE 36
#define A_BUF (128 * A_STRIDE)
#define B_BUF (256 * A_STRIDE)
#define SMEM_FLOATS (2 * A_BUF + 2 * B_BUF)

__global__ __launch_bounds__(512, 1) void k_attn_gemm_mma(
    const float* __restrict__ enc, const float* __restrict__ b_ep,
    const float* __restrict__ w_v) {
    extern __shared__ float sm[];
    float* As = sm;                 // [2][128][36]
    float* Bs = sm + 2 * A_BUF;     // [2][256][36]

    const int tid = threadIdx.x;
    const int lane = tid & 31, wid = tid >> 5;
    const int warp_m = wid & 3, warp_n = wid >> 2;   // 4 x 4
    const int row0 = blockIdx.x * 128, n0 = blockIdx.y * 256;
    const int qr = lane >> 2, qc = lane & 3;

    const float* Ag = enc + (size_t)row0 * HID;
    const float* Bg = g_Wep_T + (size_t)n0 * HID;

    const uint32_t sA = (uint32_t)__cvta_generic_to_shared(As);
    const uint32_t sB = (uint32_t)__cvta_generic_to_shared(Bs);

    const int ar0 = tid >> 3, ac0 = (tid & 7) * 4;
    // prefetch chunk 0 into buf 0
    {
        #pragma unroll
        for (int i = 0; i < 2; i++) {
            int r = ar0 + i * 64;
            cp_async16(sA + (r * A_STRIDE + ac0) * 4, Ag + (size_t)r * HID + ac0);
        }
        #pragma unroll
        for (int i = 0; i < 4; i++) {
            int r = ar0 + i * 64;
            cp_async16(sB + (r * A_STRIDE + ac0) * 4, Bg + (size_t)r * HID + ac0);
        }
        CP_COMMIT();
    }

    float acc[2][8][4];
    #pragma unroll
    for (int m = 0; m < 2; m++)
        #pragma unroll
        for (int j = 0; j < 8; j++)
            #pragma unroll
            for (int i = 0; i < 4; i++) acc[m][j][i] = 0.f;

    for (int c = 0; c < 16; c++) {
        const int buf = c & 1;
        if (c < 15) {
            const int nb = (c + 1) & 1;
            const int k0 = (c + 1) * 32;
            #pragma unroll
            for (int i = 0; i < 2; i++) {
                int r = ar0 + i * 64;
                cp_async16(sA + (nb * A_BUF + r * A_STRIDE + ac0) * 4,
                           Ag + (size_t)r * HID + k0 + ac0);
            }
            #pragma unroll
            for (int i = 0; i < 4; i++) {
                int r = ar0 + i * 64;
                cp_async16(sB + (nb * B_BUF + r * A_STRIDE + ac0) * 4,
                           Bg + (size_t)r * HID + k0 + ac0);
            }
            CP_COMMIT();
            CP_WAIT(1);
        } else {
            CP_WAIT(0);
        }
        __syncthreads();

        const float* Ab = As + buf * A_BUF;
        const float* Bb = Bs + buf * B_BUF;
        #pragma unroll
        for (int ks = 0; ks < 4; ks++) {
            const int kk = ks * 8;
            uint32_t a[2][4];
            #pragma unroll
            for (int m = 0; m < 2; m++) {
                int br = warp_m * 32 + m * 16 + qr;
                a[m][0] = __float_as_uint(Ab[br * A_STRIDE + kk + qc]);
                a[m][1] = __float_as_uint(Ab[(br + 8) * A_STRIDE + kk + qc]);
                a[m][2] = __float_as_uint(Ab[br * A_STRIDE + kk + qc + 4]);
                a[m][3] = __float_as_uint(Ab[(br + 8) * A_STRIDE + kk + qc + 4]);
            }
            uint32_t b[8][2];
            #pragma unroll
            for (int j = 0; j < 8; j++) {
                int bn = warp_n * 64 + j * 8 + qr;
                b[j][0] = __float_as_uint(Bb[bn * A_STRIDE + kk + qc]);
                b[j][1] = __float_as_uint(Bb[bn * A_STRIDE + kk + qc + 4]);
            }
            #pragma unroll
            for (int m = 0; m < 2; m++)
                #pragma unroll
                for (int j = 0; j < 8; j++)
                    mma_tf32(acc[m][j], a[m], b[j]);
        }
        __syncthreads();
    }

    // hoist per-column b_ep, w_v
    float bep_r[16], wv_r[16];
    #pragma unroll
    for (int j = 0; j < 8; j++) {
        int cc = n0 + warp_n * 64 + j * 8 + qc * 2;
        bep_r[j * 2] = b_ep[cc];     bep_r[j * 2 + 1] = b_ep[cc + 1];
        wv_r[j * 2]  = w_v[cc];      wv_r[j * 2 + 1]  = w_v[cc + 1];
    }

    // epilogue: tanh + dot(w_v), quad reduce, deterministic partial per (y,warp_n)
    #pragma unroll
    for (int g = 0; g < 4; g++) {
        int m = g >> 1;
        int lr = warp_m * 32 + m * 16 + (g & 1) * 8 + qr;
        int r = row0 + lr;
        int bb = r & 255;
        const float* hid = g_hidden_attn + (size_t)bb * HID + n0 + warp_n * 64;
        const int i0 = (g & 1) * 2;
        float p = 0.f;
        #pragma unroll
        for (int j = 0; j < 8; j++) {
            int cl = j * 8 + qc * 2;
            float v0 = acc[m][j][i0]     + bep_r[j * 2]     + hid[cl];
            float v1 = acc[m][j][i0 + 1] + bep_r[j * 2 + 1] + hid[cl + 1];
            p += tanh_fast(v0) * wv_r[j * 2] + tanh_fast(v1) * wv_r[j * 2 + 1];
        }
        p += __shfl_xor_sync(0xffffffffu, p, 1);
        p += __shfl_xor_sync(0xffffffffu, p, 2);
        if (qc == 0) {
            int t = r >> 8;
            g_scores_part[blockIdx.y * 4 + warp_n][bb * TSEQ + t] = p;
        }
    }
}

// ===== K_C1: softmax over t (scores from 8 partials) =====
__global__ __launch_bounds__(256) void k_softmax(float* __restrict__ out_attn) {
    int b = blockIdx.x, tid = threadIdx.x;
    __shared__ float sw[TSEQ];
    __shared__ float red[256];

    float lm = -1e30f;
    for (int t = tid; t < TSEQ; t += 256) {
        float s = 0.f;
        #pragma unroll
        for (int q = 0; q < 8; q++) s += g_scores_part[q][b * TSEQ + t];
        sw[t] = s;
        lm = fmaxf(lm, s);
    }
    red[tid] = lm;
    __syncthreads();
    for (int off = 128; off > 0; off >>= 1) {
        if (tid < off) red[tid] = fmaxf(red[tid], red[tid + off]);
        __syncthreads();
    }
    float m = red[0];
    __syncthreads();
    float ls = 0.f;
    for (int t = tid; t < TSEQ; t += 256) {
        float e = __expf(sw[t] - m);
        sw[t] = e;
        ls += e;
    }
    red[tid] = ls;
    __syncthreads();
    for (int off = 128; off > 0; off >>= 1) {
        if (tid < off) red[tid] += red[tid + off];
        __syncthreads();
    }
    float inv = 1.f / red[0];
    __syncthreads();
    for (int t = tid; t < TSEQ; t += 256)
        out_attn[b * TSEQ + t] = sw[t] * inv;
}

// ===== K_C2: context partials over t-chunks; grid (BATCH, 4) =====
__global__ __launch_bounds__(256) void k_context(
    const float* __restrict__ enc, const float* __restrict__ attn) {
    int b = blockIdx.x, ch = blockIdx.y, tid = threadIdx.x;
    __shared__ float sw[TCHUNK];
    for (int t = tid; t < TCHUNK; t += 256)
        sw[t] = attn[b * TSEQ + ch * TCHUNK + t];
    __syncthreads();
    float acc0 = 0.f, acc1 = 0.f;
    const float* ep = enc + (size_t)(ch * TCHUNK) * (BATCH * HID) + b * HID + tid;
    #pragma unroll 4
    for (int t = 0; t < TCHUNK; t++) {
        float w = sw[t];
        acc0 += ep[(size_t)t * (BATCH * HID)] * w;
        acc1 += ep[(size_t)t * (BATCH * HID) + 256] * w;
    }
    g_ctx_part[ch][b * HID + tid] = acc0;
    g_ctx_part[ch][b * HID + tid + 256] = acc1;
}

// ===== K_C3: combine context partials (deterministic order) =====
__global__ __launch_bounds__(256) void k_ctx_combine() {
    int idx = blockIdx.x * 256 + threadIdx.x;
    g_context[idx] = ((g_ctx_part[0][idx] + g_ctx_part[1][idx])
                    + g_ctx_part[2][idx]) + g_ctx_part[3][idx];
}

// ===== argmax + embed =====
__global__ __launch_bounds__(64) void k_argmax_embed(
    const float* __restrict__ in_char, const float* __restrict__ emb) {
    int b = blockIdx.x, tid = threadIdx.x;
    __shared__ int s_idx;
    if (tid < 32) {
        float bv = -1e30f; int bi = 0;
        for (int i = tid; i < VOCAB; i += 32) {
            float v = in_char[b * VOCAB + i];
            if (v > bv) { bv = v; bi = i; }
        }
        #pragma unroll
        for (int off = 16; off > 0; off >>= 1) {
            float ov = __shfl_down_sync(0xffffffffu, bv, off);
            int   oi = __shfl_down_sync(0xffffffffu, bi, off);
            if (ov > bv || (ov == bv && oi < bi)) { bv = ov; bi = oi; }
        }
        if (tid == 0) s_idx = bi;
    }
    __syncthreads();
    int t1 = s_idx;
    if (tid < EMBED) g_indec[b * INDEC_LD + tid] = emb[t1 * EMBED + tid];
    if (tid >= EMBED && tid < EMBED + 4)
        g_indec[b * INDEC_LD + 300 + (tid - EMBED)] = 0.f;
}

// ===== generic tiled GEMM (tail) =====
__global__ __launch_bounds__(256) void k_gemm_tail(
    const float* __restrict__ A, int lda,
    const float* __restrict__ B, int ldb,
    const float* __restrict__ bias,
    float* __restrict__ C, int ldc, int N, int K) {
    __shared__ float As[8][128];
    __shared__ float Bs[8][128];

    const int row0 = blockIdx.x * 128;
    const int n0   = blockIdx.y * 128;
    const int tid  = threadIdx.x;
    const int tx   = tid & 15;
    const int ty   = tid >> 4;

    float acc[8][8];
    #pragma unroll
    for (int i = 0; i < 8; i++)
        #pragma unroll
        for (int j = 0; j < 8; j++) acc[i][j] = 0.f;

    const int arow = tid >> 1;
    const int aseg = (tid & 1) * 4;
    const int Kpad = (K + 7) & ~7;

    for (int k0 = 0; k0 < Kpad; k0 += 8) {
        float4 av = *(const float4*)(A + (size_t)(row0 + arow) * lda + k0 + aseg);
        As[aseg + 0][arow] = av.x;
        As[aseg + 1][arow] = av.y;
        As[aseg + 2][arow] = av.z;
        As[aseg + 3][arow] = av.w;
        #pragma unroll
        for (int j = 0; j < 4; j++) {
            int e = tid + j * 256;
            int bk = e >> 7, bn = e & 127;
            int gk = k0 + bk, gn = n0 + bn;
            Bs[bk][bn] = (gk < K && gn < N) ? B[(size_t)gk * ldb + gn] : 0.f;
        }
        __syncthreads();
        #pragma unroll
        for (int k = 0; k < 8; k++) {
            float a[8], bb[8];
            float4 a0 = *(const float4*)&As[k][ty * 8];
            float4 a1 = *(const float4*)&As[k][ty * 8 + 4];
            float4 b0 = *(const float4*)&Bs[k][tx * 8];
            float4 b1 = *(const float4*)&Bs[k][tx * 8 + 4];
            a[0]=a0.x;a[1]=a0.y;a[2]=a0.z;a[3]=a0.w;a[4]=a1.x;a[5]=a1.y;a[6]=a1.z;a[7]=a1.w;
            bb[0]=b0.x;bb[1]=b0.y;bb[2]=b0.z;bb[3]=b0.w;bb[4]=b1.x;bb[5]=b1.y;bb[6]=b1.z;bb[7]=b1.w;
            #pragma unroll
            for (int i = 0; i < 8; i++)
                #pragma unroll
                for (int j = 0; j < 8; j++) acc[i][j] += a[i] * bb[j];
        }
        __syncthreads();
    }

    #pragma unroll
    for (int i = 0; i < 8; i++) {
        int r = row0 + ty * 8 + i;
        #pragma unroll
        for (int j = 0; j < 8; j++) {
            int c = n0 + tx * 8 + j;
            if (c < N) C[(size_t)r * ldc + c] = acc[i][j] + bias[c];
        }
    }
}

// ===== GRU gates =====
__global__ __launch_bounds__(256) void k_gates(
    const float* __restrict__ hidden, float* __restrict__ out_newh) {
    int idx = blockIdx.x * 256 + threadIdx.x;
    int b = idx >> 9, j = idx & 511;
    const float* gi = g_gi + b * 3 * HID;
    const float* gh = g_gh + b * 3 * HID;
    float r = sigmoidf_(gi[j] + gh[j]);
    float z = sigmoidf_(gi[HID + j] + gh[HID + j]);
    float n = tanhf(gi[2 * HID + j] + r * gh[2 * HID + j]);
    float h = hidden[idx];
    out_newh[idx] = (1.f - z) * n + z * h;
}

// ===== output softmax =====
__global__ __launch_bounds__(128) void k_out_softmax(
    const float* __restrict__ newh, const float* __restrict__ W_out,
    const float* __restrict__ b_out, float* __restrict__ out_logits) {
    int b = blockIdx.x, tid = threadIdx.x;
    __shared__ float sh[HID];
    __shared__ float se[VOCAB];
    __shared__ float sred[2];
    #pragma unroll
    for (int i = 0; i < 4; i++) sh[tid + i * 128] = newh[b * HID + tid + i * 128];
    __syncthreads();
    if (tid < VOCAB) {
        float acc = b_out[tid];
        #pragma unroll 8
        for (int k = 0; k < HID; k++) acc += sh[k] * W_out[k * VOCAB + tid];
        se[tid] = acc;
    }
    __syncthreads();
    if (tid == 0) {
        float m = se[0];
        for (int i = 1; i < VOCAB; i++) m = fmaxf(m, se[i]);
        sred[0] = m;
    }
    __syncthreads();
    if (tid < VOCAB) se[tid] = __expf(se[tid] - sred[0]);
    __syncthreads();
    if (tid == 0) {
        float s = 0.f;
        for (int i = 0; i < VOCAB; i++) s += se[i];
        sred[1] = 1.f / s;
    }
    __syncthreads();
    if (tid < VOCAB) out_logits[b * VOCAB + tid] = se[tid] * sred[1];
}

// =============================== launcher ===============================
extern "C" void kernel_launch(void* const* d_in, const int* in_sizes, int n_in,
                              void* d_out, int out_size) {
    const float* in_char = (const float*)d_in[0];
    const float* hidden  = (const float*)d_in[1];
    const float* enc     = (const float*)d_in[2];
    const float* W_hp    = (const float*)d_in[3];
    const float* b_hp    = (const float*)d_in[4];
    const float* W_ep    = (const float*)d_in[5];
    const float* b_ep    = (const float*)d_in[6];
    const float* w_v     = (const float*)d_in[7];
    const float* W_cs    = (const float*)d_in[9];
    const float* b_cs    = (const float*)d_in[10];
    const float* emb     = (const float*)d_in[11];
    const float* W_ih    = (const float*)d_in[12];
    const float* b_ih    = (const float*)d_in[13];
    const float* W_hh    = (const float*)d_in[14];
    const float* b_hh    = (const float*)d_in[15];
    const float* W_out   = (const float*)d_in[16];
    const float* b_out   = (const float*)d_in[17];

    float* out = (float*)d_out;
    float* out_logits = out;
    float* out_newh   = out + BATCH * VOCAB;
    float* out_attn   = out + BATCH * VOCAB + BATCH * HID;

    float* p_indec; cudaGetSymbolAddress((void**)&p_indec, g_indec);
    float* p_gi;    cudaGetSymbolAddress((void**)&p_gi, g_gi);
    float* p_gh;    cudaGetSymbolAddress((void**)&p_gh, g_gh);
    float* p_ctx;   cudaGetSymbolAddress((void**)&p_ctx, g_context);

    // idempotent, called every time (no static guards allowed)
    cudaFuncSetAttribute(k_attn_gemm_mma,
                         cudaFuncAttributeMaxDynamicSharedMemorySize,
                         SMEM_FLOATS * 4);

    // attention path
    k_transpose_wep<<<dim3(16, 16), 256>>>(W_ep);
    k_hidden_attn<<<BATCH, 256>>>(hidden, W_hp, b_hp);
    k_attn_gemm_mma<<<dim3((TSEQ * BATCH) / 128, 2), 512, SMEM_FLOATS * 4>>>(enc, b_ep, w_v);
    k_softmax<<<BATCH, 256>>>(out_attn);
    k_context<<<dim3(BATCH, 4), 256>>>(enc, out_attn);
    k_ctx_combine<<<(BATCH * HID) / 256, 256>>>();

    // decoder tail
    k_argmax_embed<<<BATCH, 64>>>(in_char, emb);
    k_gemm_tail<<<dim3(2, 2), 256>>>(p_ctx, HID, W_cs, 250, b_cs,
                                     p_indec + EMBED, INDEC_LD, 250, HID);
    k_gemm_tail<<<dim3(2, 12), 256>>>(p_indec, INDEC_LD, W_ih, 3 * HID, b_ih,
                                      p_gi, 3 * HID, 3 * HID, 300);
    k_gemm_tail<<<dim3(2, 12), 256>>>(hidden, HID, W_hh, 3 * HID, b_hh,
                                      p_gh, 3 * HID, 3 * HID, HID);
    k_gates<<<(BATCH * HID) / 256, 256>>>(hidden, out_newh);
    k_out_softmax<<<BATCH, 128>>>(out_newh, W_out, b_out, out_logits);
}

// round 9
// speedup vs baseline: 3.1883x; 1.1473x over previous
#include <cuda_runtime.h>
#include <cuda_fp16.h>
#include <math.h>
#include <cstdint>

#define HID 512
#define BATCH 256
#define TSEQ 600
#define VOCAB 83
#define EMBED 50
#define INDEC_LD 304
#define TCHUNK 150

// -------- scratch --------
__device__ float g_hidden_attn[BATCH * HID];
__device__ float g_scores_part[8][BATCH * TSEQ];
__device__ float g_context[BATCH * HID];
__device__ float g_ctx_part[4][BATCH * HID];
__device__ float g_indec[BATCH * INDEC_LD];
__device__ float g_gi[BATCH * 3 * HID];
__device__ float g_gh[BATCH * 3 * HID];
__device__ __half g_encH[(size_t)TSEQ * BATCH * HID];   // fp16 copy of enc (157 MB)
__device__ __half g_WepH_T[HID * HID];                  // [n][k] fp16 transposed W_ep

__device__ __forceinline__ float tanh_fast(float x) {
    float y; asm("tanh.approx.f32 %0, %1;" : "=f"(y) : "f"(x)); return y;
}
__device__ __forceinline__ float sigmoidf_(float x) {
    return 1.0f / (1.0f + __expf(-x));
}
__device__ __forceinline__ void mma_f16(float* c, const uint32_t* a, const uint32_t* b) {
    asm volatile(
        "mma.sync.aligned.m16n8k16.row.col.f32.f16.f16.f32 "
        "{%0,%1,%2,%3}, {%4,%5,%6,%7}, {%8,%9}, {%0,%1,%2,%3};"
        : "+f"(c[0]), "+f"(c[1]), "+f"(c[2]), "+f"(c[3])
        : "r"(a[0]), "r"(a[1]), "r"(a[2]), "r"(a[3]), "r"(b[0]), "r"(b[1]));
}
__device__ __forceinline__ void cp_async16(uint32_t dst, const void* src) {
    asm volatile("cp.async.cg.shared.global [%0], [%1], 16;" :: "r"(dst), "l"(src));
}
#define CP_COMMIT() asm volatile("cp.async.commit_group;" ::: "memory")
#define CP_WAIT(n)  asm volatile("cp.async.wait_group %0;" :: "n"(n) : "memory")

// ===== convert enc f32 -> f16 (8 elems/thread) =====
__global__ __launch_bounds__(256) void k_convert_enc(const float* __restrict__ enc) {
    size_t i8 = ((size_t)blockIdx.x * 256 + threadIdx.x) * 8;
    float4 v0 = *(const float4*)(enc + i8);
    float4 v1 = *(const float4*)(enc + i8 + 4);
    __half2 h[4];
    h[0] = __halves2half2(__float2half_rn(v0.x), __float2half_rn(v0.y));
    h[1] = __halves2half2(__float2half_rn(v0.z), __float2half_rn(v0.w));
    h[2] = __halves2half2(__float2half_rn(v1.x), __float2half_rn(v1.y));
    h[3] = __halves2half2(__float2half_rn(v1.z), __float2half_rn(v1.w));
    const uint32_t* hu = (const uint32_t*)h;
    *(uint2*)(g_encH + i8)     = make_uint2(hu[0], hu[1]);
    *(uint2*)(g_encH + i8 + 4) = make_uint2(hu[2], hu[3]);
}

// ===== transpose W_ep -> fp16: g_WepH_T[n][k] = h(W_ep[k][n]) =====
__global__ __launch_bounds__(256) void k_transpose_wep(const float* __restrict__ W) {
    __shared__ float t[32][33];
    int bx = blockIdx.x * 32, by = blockIdx.y * 32;
    int x = threadIdx.x & 31, y = threadIdx.x >> 5;
    #pragma unroll
    for (int i = 0; i < 32; i += 8)
        t[y + i][x] = W[(size_t)(by + y + i) * HID + bx + x];
    __syncthreads();
    #pragma unroll
    for (int i = 0; i < 32; i += 8)
        g_WepH_T[(size_t)(bx + y + i) * HID + by + x] = __float2half_rn(t[x][y + i]);
}

// ===== K_A: hidden_attn = hidden @ W_hp + b_hp =====
__global__ __launch_bounds__(256) void k_hidden_attn(
    const float* __restrict__ hidden, const float* __restrict__ W_hp,
    const float* __restrict__ b_hp) {
    int b = blockIdx.x, tid = threadIdx.x;
    __shared__ float sh[HID];
    sh[tid] = hidden[b * HID + tid];
    sh[tid + 256] = hidden[b * HID + tid + 256];
    __syncthreads();
    #pragma unroll
    for (int jj = 0; jj < 2; jj++) {
        int n = tid + jj * 256;
        float acc = b_hp[n];
        #pragma unroll 8
        for (int k = 0; k < HID; k++) acc += sh[k] * W_hp[k * HID + n];
        g_hidden_attn[b * HID + n] = acc;
    }
}

// ===== K_B: fp16 m16n8k16 fused GEMM, cp.async double-buffered =====
// grid (1200, 2), 512 threads = 16 warps (4 M x 4 N). CTA tile 128x256, warp 32x64.
#define ASTR 40                     // halves per row (32 data + 8 pad), 80 B
#define A_BUF_H (128 * ASTR)        // halves
#define B_BUF_H (256 * ASTR)
#define SMEM_BYTES ((A_BUF_H + B_BUF_H) * 2 * 2)

__global__ __launch_bounds__(512, 1) void k_attn_gemm_mma(
    const float* __restrict__ b_ep, const float* __restrict__ w_v) {
    extern __shared__ __half sm[];
    __half* As = sm;                      // [2][128][40]
    __half* Bs = sm + 2 * A_BUF_H;        // [2][256][40]

    const int tid = threadIdx.x;
    const int lane = tid & 31, wid = tid >> 5;
    const int warp_m = wid & 3, warp_n = wid >> 2;
    const int row0 = blockIdx.x * 128, n0 = blockIdx.y * 256;
    const int qr = lane >> 2, qc = lane & 3;

    const __half* Ag = g_encH + (size_t)row0 * HID;
    const __half* Bg = g_WepH_T + (size_t)n0 * HID;

    const uint32_t sA = (uint32_t)__cvta_generic_to_shared(As);
    const uint32_t sB = (uint32_t)__cvta_generic_to_shared(Bs);

    const int lr = tid >> 2, lseg = (tid & 3) * 8;
    {
        cp_async16(sA + (lr * ASTR + lseg) * 2, Ag + (size_t)lr * HID + lseg);
        cp_async16(sB + (lr * ASTR + lseg) * 2, Bg + (size_t)lr * HID + lseg);
        cp_async16(sB + ((lr + 128) * ASTR + lseg) * 2, Bg + (size_t)(lr + 128) * HID + lseg);
        CP_COMMIT();
    }

    float acc[2][8][4];
    #pragma unroll
    for (int m = 0; m < 2; m++)
        #pragma unroll
        for (int j = 0; j < 8; j++)
            #pragma unroll
            for (int i = 0; i < 4; i++) acc[m][j][i] = 0.f;

    for (int c = 0; c < 16; c++) {
        const int buf = c & 1;
        if (c < 15) {
            const int nb = (c + 1) & 1;
            const int k0 = (c + 1) * 32;
            cp_async16(sA + (nb * A_BUF_H + lr * ASTR + lseg) * 2,
                       Ag + (size_t)lr * HID + k0 + lseg);
            cp_async16(sB + (nb * B_BUF_H + lr * ASTR + lseg) * 2,
                       Bg + (size_t)lr * HID + k0 + lseg);
            cp_async16(sB + (nb * B_BUF_H + (lr + 128) * ASTR + lseg) * 2,
                       Bg + (size_t)(lr + 128) * HID + k0 + lseg);
            CP_COMMIT();
            CP_WAIT(1);
        } else {
            CP_WAIT(0);
        }
        __syncthreads();

        const __half* Ab = As + buf * A_BUF_H;
        const __half* Bb = Bs + buf * B_BUF_H;
        #pragma unroll
        for (int ks = 0; ks < 2; ks++) {
            const int kk = ks * 16;
            uint32_t a[2][4];
            #pragma unroll
            for (int m = 0; m < 2; m++) {
                int br = warp_m * 32 + m * 16 + qr;
                a[m][0] = *(const uint32_t*)&Ab[br * ASTR + kk + 2 * qc];
                a[m][1] = *(const uint32_t*)&Ab[(br + 8) * ASTR + kk + 2 * qc];
                a[m][2] = *(const uint32_t*)&Ab[br * ASTR + kk + 2 * qc + 8];
                a[m][3] = *(const uint32_t*)&Ab[(br + 8) * ASTR + kk + 2 * qc + 8];
            }
            uint32_t b[8][2];
            #pragma unroll
            for (int j = 0; j < 8; j++) {
                int bn = warp_n * 64 + j * 8 + qr;
                b[j][0] = *(const uint32_t*)&Bb[bn * ASTR + kk + 2 * qc];
                b[j][1] = *(const uint32_t*)&Bb[bn * ASTR + kk + 2 * qc + 8];
            }
            #pragma unroll
            for (int m = 0; m < 2; m++)
                #pragma unroll
                for (int j = 0; j < 8; j++)
                    mma_f16(acc[m][j], a[m], b[j]);
        }
        __syncthreads();
    }

    // hoist per-column b_ep, w_v
    float bep_r[16], wv_r[16];
    #pragma unroll
    for (int j = 0; j < 8; j++) {
        int cc = n0 + warp_n * 64 + j * 8 + qc * 2;
        bep_r[j * 2] = b_ep[cc];     bep_r[j * 2 + 1] = b_ep[cc + 1];
        wv_r[j * 2]  = w_v[cc];      wv_r[j * 2 + 1]  = w_v[cc + 1];
    }

    // epilogue: tanh + dot(w_v), quad reduce, deterministic partial per (y,warp_n)
    #pragma unroll
    for (int g = 0; g < 4; g++) {
        int m = g >> 1;
        int lrr = warp_m * 32 + m * 16 + (g & 1) * 8 + qr;
        int r = row0 + lrr;
        int bb = r & 255;
        const float* hid = g_hidden_attn + (size_t)bb * HID + n0 + warp_n * 64;
        const int i0 = (g & 1) * 2;
        float p = 0.f;
        #pragma unroll
        for (int j = 0; j < 8; j++) {
            int cl = j * 8 + qc * 2;
            float v0 = acc[m][j][i0]     + bep_r[j * 2]     + hid[cl];
            float v1 = acc[m][j][i0 + 1] + bep_r[j * 2 + 1] + hid[cl + 1];
            p += tanh_fast(v0) * wv_r[j * 2] + tanh_fast(v1) * wv_r[j * 2 + 1];
        }
        p += __shfl_xor_sync(0xffffffffu, p, 1);
        p += __shfl_xor_sync(0xffffffffu, p, 2);
        if (qc == 0) {
            int t = r >> 8;
            g_scores_part[blockIdx.y * 4 + warp_n][bb * TSEQ + t] = p;
        }
    }
}

// ===== K_C1: softmax over t (scores from 8 partials) =====
__global__ __launch_bounds__(256) void k_softmax(float* __restrict__ out_attn) {
    int b = blockIdx.x, tid = threadIdx.x;
    __shared__ float sw[TSEQ];
    __shared__ float red[256];

    float lm = -1e30f;
    for (int t = tid; t < TSEQ; t += 256) {
        float s = 0.f;
        #pragma unroll
        for (int q = 0; q < 8; q++) s += g_scores_part[q][b * TSEQ + t];
        sw[t] = s;
        lm = fmaxf(lm, s);
    }
    red[tid] = lm;
    __syncthreads();
    for (int off = 128; off > 0; off >>= 1) {
        if (tid < off) red[tid] = fmaxf(red[tid], red[tid + off]);
        __syncthreads();
    }
    float m = red[0];
    __syncthreads();
    float ls = 0.f;
    for (int t = tid; t < TSEQ; t += 256) {
        float e = __expf(sw[t] - m);
        sw[t] = e;
        ls += e;
    }
    red[tid] = ls;
    __syncthreads();
    for (int off = 128; off > 0; off >>= 1) {
        if (tid < off) red[tid] += red[tid + off];
        __syncthreads();
    }
    float inv = 1.f / red[0];
    __syncthreads();
    for (int t = tid; t < TSEQ; t += 256)
        out_attn[b * TSEQ + t] = sw[t] * inv;
}

// ===== K_C2: context partials over t-chunks; grid (BATCH, 4) =====
__global__ __launch_bounds__(256) void k_context(
    const float* __restrict__ enc, const float* __restrict__ attn) {
    int b = blockIdx.x, ch = blockIdx.y, tid = threadIdx.x;
    __shared__ float sw[TCHUNK];
    for (int t = tid; t < TCHUNK; t += 256)
        sw[t] = attn[b * TSEQ + ch * TCHUNK + t];
    __syncthreads();
    float acc0 = 0.f, acc1 = 0.f;
    const float* ep = enc + (size_t)(ch * TCHUNK) * (BATCH * HID) + b * HID + tid;
    #pragma unroll 4
    for (int t = 0; t < TCHUNK; t++) {
        float w = sw[t];
        acc0 += ep[(size_t)t * (BATCH * HID)] * w;
        acc1 += ep[(size_t)t * (BATCH * HID) + 256] * w;
    }
    g_ctx_part[ch][b * HID + tid] = acc0;
    g_ctx_part[ch][b * HID + tid + 256] = acc1;
}

// ===== K_C3: combine context partials (deterministic order) =====
__global__ __launch_bounds__(256) void k_ctx_combine() {
    int idx = blockIdx.x * 256 + threadIdx.x;
    g_context[idx] = ((g_ctx_part[0][idx] + g_ctx_part[1][idx])
                    + g_ctx_part[2][idx]) + g_ctx_part[3][idx];
}

// ===== argmax + embed =====
__global__ __launch_bounds__(64) void k_argmax_embed(
    const float* __restrict__ in_char, const float* __restrict__ emb) {
    int b = blockIdx.x, tid = threadIdx.x;
    __shared__ int s_idx;
    if (tid < 32) {
        float bv = -1e30f; int bi = 0;
        for (int i = tid; i < VOCAB; i += 32) {
            float v = in_char[b * VOCAB + i];
            if (v > bv) { bv = v; bi = i; }
        }
        #pragma unroll
        for (int off = 16; off > 0; off >>= 1) {
            float ov = __shfl_down_sync(0xffffffffu, bv, off);
            int   oi = __shfl_down_sync(0xffffffffu, bi, off);
            if (ov > bv || (ov == bv && oi < bi)) { bv = ov; bi = oi; }
        }
        if (tid == 0) s_idx = bi;
    }
    __syncthreads();
    int t1 = s_idx;
    if (tid < EMBED) g_indec[b * INDEC_LD + tid] = emb[t1 * EMBED + tid];
    if (tid >= EMBED && tid < EMBED + 4)
        g_indec[b * INDEC_LD + 300 + (tid - EMBED)] = 0.f;
}

// ===== generic tiled GEMM (tail) =====
__global__ __launch_bounds__(256) void k_gemm_tail(
    const float* __restrict__ A, int lda,
    const float* __restrict__ B, int ldb,
    const float* __restrict__ bias,
    float* __restrict__ C, int ldc, int N, int K) {
    __shared__ float As[8][128];
    __shared__ float Bs[8][128];

    const int row0 = blockIdx.x * 128;
    const int n0   = blockIdx.y * 128;
    const int tid  = threadIdx.x;
    const int tx   = tid & 15;
    const int ty   = tid >> 4;

    float acc[8][8];
    #pragma unroll
    for (int i = 0; i < 8; i++)
        #pragma unroll
        for (int j = 0; j < 8; j++) acc[i][j] = 0.f;

    const int arow = tid >> 1;
    const int aseg = (tid & 1) * 4;
    const int Kpad = (K + 7) & ~7;

    for (int k0 = 0; k0 < Kpad; k0 += 8) {
        float4 av = *(const float4*)(A + (size_t)(row0 + arow) * lda + k0 + aseg);
        As[aseg + 0][arow] = av.x;
        As[aseg + 1][arow] = av.y;
        As[aseg + 2][arow] = av.z;
        As[aseg + 3][arow] = av.w;
        #pragma unroll
        for (int j = 0; j < 4; j++) {
            int e = tid + j * 256;
            int bk = e >> 7, bn = e & 127;
            int gk = k0 + bk, gn = n0 + bn;
            Bs[bk][bn] = (gk < K && gn < N) ? B[(size_t)gk * ldb + gn] : 0.f;
        }
        __syncthreads();
        #pragma unroll
        for (int k = 0; k < 8; k++) {
            float a[8], bb[8];
            float4 a0 = *(const float4*)&As[k][ty * 8];
            float4 a1 = *(const float4*)&As[k][ty * 8 + 4];
            float4 b0 = *(const float4*)&Bs[k][tx * 8];
            float4 b1 = *(const float4*)&Bs[k][tx * 8 + 4];
            a[0]=a0.x;a[1]=a0.y;a[2]=a0.z;a[3]=a0.w;a[4]=a1.x;a[5]=a1.y;a[6]=a1.z;a[7]=a1.w;
            bb[0]=b0.x;bb[1]=b0.y;bb[2]=b0.z;bb[3]=b0.w;bb[4]=b1.x;bb[5]=b1.y;bb[6]=b1.z;bb[7]=b1.w;
            #pragma unroll
            for (int i = 0; i < 8; i++)
                #pragma unroll
                for (int j = 0; j < 8; j++) acc[i][j] += a[i] * bb[j];
        }
        __syncthreads();
    }

    #pragma unroll
    for (int i = 0; i < 8; i++) {
        int r = row0 + ty * 8 + i;
        #pragma unroll
        for (int j = 0; j < 8; j++) {
            int c = n0 + tx * 8 + j;
            if (c < N) C[(size_t)r * ldc + c] = acc[i][j] + bias[c];
        }
    }
}

// ===== GRU gates =====
__global__ __launch_bounds__(256) void k_gates(
    const float* __restrict__ hidden, float* __restrict__ out_newh) {
    int idx = blockIdx.x * 256 + threadIdx.x;
    int b = idx >> 9, j = idx & 511;
    const float* gi = g_gi + b * 3 * HID;
    const float* gh = g_gh + b * 3 * HID;
    float r = sigmoidf_(gi[j] + gh[j]);
    float z = sigmoidf_(gi[HID + j] + gh[HID + j]);
    float n = tanhf(gi[2 * HID + j] + r * gh[2 * HID + j]);
    float h = hidden[idx];
    out_newh[idx] = (1.f - z) * n + z * h;
}

// ===== output softmax =====
__global__ __launch_bounds__(128) void k_out_softmax(
    const float* __restrict__ newh, const float* __restrict__ W_out,
    const float* __restrict__ b_out, float* __restrict__ out_logits) {
    int b = blockIdx.x, tid = threadIdx.x;
    __shared__ float sh[HID];
    __shared__ float se[VOCAB];
    __shared__ float sred[2];
    #pragma unroll
    for (int i = 0; i < 4; i++) sh[tid + i * 128] = newh[b * HID + tid + i * 128];
    __syncthreads();
    if (tid < VOCAB) {
        float acc = b_out[tid];
        #pragma unroll 8
        for (int k = 0; k < HID; k++) acc += sh[k] * W_out[k * VOCAB + tid];
        se[tid] = acc;
    }
    __syncthreads();
    if (tid == 0) {
        float m = se[0];
        for (int i = 1; i < VOCAB; i++) m = fmaxf(m, se[i]);
        sred[0] = m;
    }
    __syncthreads();
    if (tid < VOCAB) se[tid] = __expf(se[tid] - sred[0]);
    __syncthreads();
    if (tid == 0) {
        float s = 0.f;
        for (int i = 0; i < VOCAB; i++) s += se[i];
        sred[1] = 1.f / s;
    }
    __syncthreads();
    if (tid < VOCAB) out_logits[b * VOCAB + tid] = se[tid] * sred[1];
}

// =============================== launcher ===============================
extern "C" void kernel_launch(void* const* d_in, const int* in_sizes, int n_in,
                              void* d_out, int out_size) {
    const float* in_char = (const float*)d_in[0];
    const float* hidden  = (const float*)d_in[1];
    const float* enc     = (const float*)d_in[2];
    const float* W_hp    = (const float*)d_in[3];
    const float* b_hp    = (const float*)d_in[4];
    const float* W_ep    = (const float*)d_in[5];
    const float* b_ep    = (const float*)d_in[6];
    const float* w_v     = (const float*)d_in[7];
    const float* W_cs    = (const float*)d_in[9];
    const float* b_cs    = (const float*)d_in[10];
    const float* emb     = (const float*)d_in[11];
    const float* W_ih    = (const float*)d_in[12];
    const float* b_ih    = (const float*)d_in[13];
    const float* W_hh    = (const float*)d_in[14];
    const float* b_hh    = (const float*)d_in[15];
    const float* W_out   = (const float*)d_in[16];
    const float* b_out   = (const float*)d_in[17];

    float* out = (float*)d_out;
    float* out_logits = out;
    float* out_newh   = out + BATCH * VOCAB;
    float* out_attn   = out + BATCH * VOCAB + BATCH * HID;

    float* p_indec; cudaGetSymbolAddress((void**)&p_indec, g_indec);
    float* p_gi;    cudaGetSymbolAddress((void**)&p_gi, g_gi);
    float* p_gh;    cudaGetSymbolAddress((void**)&p_gh, g_gh);
    float* p_ctx;   cudaGetSymbolAddress((void**)&p_ctx, g_context);

    cudaFuncSetAttribute(k_attn_gemm_mma,
                         cudaFuncAttributeMaxDynamicSharedMemorySize, SMEM_BYTES);

    // attention path
    k_convert_enc<<<(TSEQ * BATCH * HID) / (8 * 256), 256>>>(enc);
    k_transpose_wep<<<dim3(16, 16), 256>>>(W_ep);
    k_hidden_attn<<<BATCH, 256>>>(hidden, W_hp, b_hp);
    k_attn_gemm_mma<<<dim3((TSEQ * BATCH) / 128, 2), 512, SMEM_BYTES>>>(b_ep, w_v);
    k_softmax<<<BATCH, 256>>>(out_attn);
    k_context<<<dim3(BATCH, 4), 256>>>(enc, out_attn);
    k_ctx_combine<<<(BATCH * HID) / 256, 256>>>();

    // decoder tail
    k_argmax_embed<<<BATCH, 64>>>(in_char, emb);
    k_gemm_tail<<<dim3(2, 2), 256>>>(p_ctx, HID, W_cs, 250, b_cs,
                                     p_indec + EMBED, INDEC_LD, 250, HID);
    k_gemm_tail<<<dim3(2, 12), 256>>>(p_indec, INDEC_LD, W_ih, 3 * HID, b_ih,
                                      p_gi, 3 * HID, 3 * HID, 300);
    k_gemm_tail<<<dim3(2, 12), 256>>>(hidden, HID, W_hh, 3 * HID, b_hh,
                                      p_gh, 3 * HID, 3 * HID, HID);
    k_gates<<<(BATCH * HID) / 256, 256>>>(hidden, out_newh);
    k_out_softmax<<<BATCH, 128>>>(out_newh, W_out, b_out, out_logits);
}

// round 11
// speedup vs baseline: 4.1516x; 1.3021x over previous
#include <cuda_runtime.h>
#include <cuda_fp16.h>
#include <math.h>
#include <cstdint>

#define HID 512
#define BATCH 256
#define TSEQ 600
#define VOCAB 83
#define EMBED 50
#define INDEC_LD 304
#define TCHUNK 150

// -------- scratch --------
__device__ float g_hidden_attn[BATCH * HID];
__device__ float g_scores_part[8][BATCH * TSEQ];
__device__ float g_context[BATCH * HID];
__device__ float g_ctx_part[4][BATCH * HID];
__device__ float g_indec[BATCH * INDEC_LD];
__device__ float g_gi[BATCH * 3 * HID];
__device__ float g_gh[BATCH * 3 * HID];
__device__ __half g_encH[(size_t)TSEQ * BATCH * HID];
__device__ __half g_WepH_T[HID * HID];

__device__ __forceinline__ float tanh_fast(float x) {
    float y; asm("tanh.approx.f32 %0, %1;" : "=f"(y) : "f"(x)); return y;
}
__device__ __forceinline__ float sigmoidf_(float x) {
    return 1.0f / (1.0f + __expf(-x));
}
__device__ __forceinline__ void mma_f16(float* c, const uint32_t* a, const uint32_t* b) {
    asm volatile(
        "mma.sync.aligned.m16n8k16.row.col.f32.f16.f16.f32 "
        "{%0,%1,%2,%3}, {%4,%5,%6,%7}, {%8,%9}, {%0,%1,%2,%3};"
        : "+f"(c[0]), "+f"(c[1]), "+f"(c[2]), "+f"(c[3])
        : "r"(a[0]), "r"(a[1]), "r"(a[2]), "r"(a[3]), "r"(b[0]), "r"(b[1]));
}
__device__ __forceinline__ void ldsm_x4(uint32_t* r, uint32_t addr) {
    asm volatile("ldmatrix.sync.aligned.m8n8.x4.shared.b16 {%0,%1,%2,%3}, [%4];"
        : "=r"(r[0]), "=r"(r[1]), "=r"(r[2]), "=r"(r[3]) : "r"(addr));
}
__device__ __forceinline__ void cp_async16(uint32_t dst, const void* src) {
    asm volatile("cp.async.cg.shared.global [%0], [%1], 16;" :: "r"(dst), "l"(src));
}
#define CP_COMMIT() asm volatile("cp.async.commit_group;" ::: "memory")
#define CP_WAIT(n)  asm volatile("cp.async.wait_group %0;" :: "n"(n) : "memory")

// ===== convert enc f32 -> f16 =====
__global__ __launch_bounds__(256) void k_convert_enc(const float* __restrict__ enc) {
    size_t i8 = ((size_t)blockIdx.x * 256 + threadIdx.x) * 8;
    float4 v0 = *(const float4*)(enc + i8);
    float4 v1 = *(const float4*)(enc + i8 + 4);
    __half2 h[4];
    h[0] = __halves2half2(__float2half_rn(v0.x), __float2half_rn(v0.y));
    h[1] = __halves2half2(__float2half_rn(v0.z), __float2half_rn(v0.w));
    h[2] = __halves2half2(__float2half_rn(v1.x), __float2half_rn(v1.y));
    h[3] = __halves2half2(__float2half_rn(v1.z), __float2half_rn(v1.w));
    const uint32_t* hu = (const uint32_t*)h;
    *(uint2*)(g_encH + i8)     = make_uint2(hu[0], hu[1]);
    *(uint2*)(g_encH + i8 + 4) = make_uint2(hu[2], hu[3]);
}

// ===== transpose W_ep -> fp16 =====
__global__ __launch_bounds__(256) void k_transpose_wep(const float* __restrict__ W) {
    __shared__ float t[32][33];
    int bx = blockIdx.x * 32, by = blockIdx.y * 32;
    int x = threadIdx.x & 31, y = threadIdx.x >> 5;
    #pragma unroll
    for (int i = 0; i < 32; i += 8)
        t[y + i][x] = W[(size_t)(by + y + i) * HID + bx + x];
    __syncthreads();
    #pragma unroll
    for (int i = 0; i < 32; i += 8)
        g_WepH_T[(size_t)(bx + y + i) * HID + by + x] = __float2half_rn(t[x][y + i]);
}

// ===== K_B: fp16 m16n8k16 GEMM, cp.async + ldmatrix =====
#define ASTR 40
#define A_BUF_H (128 * ASTR)
#define B_BUF_H (256 * ASTR)
#define SMEM_BYTES ((A_BUF_H + B_BUF_H) * 2 * 2)

__global__ __launch_bounds__(512, 1) void k_attn_gemm_mma(
    const float* __restrict__ b_ep, const float* __restrict__ w_v) {
    extern __shared__ __half sm[];
    __half* As = sm;                      // [2][128][40]
    __half* Bs = sm + 2 * A_BUF_H;        // [2][256][40]

    const int tid = threadIdx.x;
    const int lane = tid & 31, wid = tid >> 5;
    const int warp_m = wid & 3, warp_n = wid >> 2;
    const int row0 = blockIdx.x * 128, n0 = blockIdx.y * 256;
    const int qr = lane >> 2, qc = lane & 3;

    const __half* Ag = g_encH + (size_t)row0 * HID;
    const __half* Bg = g_WepH_T + (size_t)n0 * HID;

    const uint32_t sA = (uint32_t)__cvta_generic_to_shared(As);
    const uint32_t sB = (uint32_t)__cvta_generic_to_shared(Bs);

    // ldmatrix lane address bases (bytes)
    const int rg = lane & 7;
    const uint32_t aoff = ((warp_m * 32 + ((lane >> 3) & 1) * 8 + rg) * ASTR
                          + ((lane >> 4) & 1) * 8) * 2;
    const uint32_t boff = ((warp_n * 64 + ((lane >> 4) & 1) * 8 + rg) * ASTR
                          + ((lane >> 3) & 1) * 8) * 2;

    const int lr = tid >> 2, lseg = (tid & 3) * 8;
    {
        cp_async16(sA + (lr * ASTR + lseg) * 2, Ag + (size_t)lr * HID + lseg);
        cp_async16(sB + (lr * ASTR + lseg) * 2, Bg + (size_t)lr * HID + lseg);
        cp_async16(sB + ((lr + 128) * ASTR + lseg) * 2, Bg + (size_t)(lr + 128) * HID + lseg);
        CP_COMMIT();
    }

    float acc[2][8][4];
    #pragma unroll
    for (int m = 0; m < 2; m++)
        #pragma unroll
        for (int j = 0; j < 8; j++)
            #pragma unroll
            for (int i = 0; i < 4; i++) acc[m][j][i] = 0.f;

    for (int c = 0; c < 16; c++) {
        const int buf = c & 1;
        if (c < 15) {
            const int nb = (c + 1) & 1;
            const int k0 = (c + 1) * 32;
            cp_async16(sA + (nb * A_BUF_H + lr * ASTR + lseg) * 2,
                       Ag + (size_t)lr * HID + k0 + lseg);
            cp_async16(sB + (nb * B_BUF_H + lr * ASTR + lseg) * 2,
                       Bg + (size_t)lr * HID + k0 + lseg);
            cp_async16(sB + (nb * B_BUF_H + (lr + 128) * ASTR + lseg) * 2,
                       Bg + (size_t)(lr + 128) * HID + k0 + lseg);
            CP_COMMIT();
            CP_WAIT(1);
        } else {
            CP_WAIT(0);
        }
        __syncthreads();

        const uint32_t abase = sA + buf * A_BUF_H * 2 + aoff;
        const uint32_t bbase = sB + buf * B_BUF_H * 2 + boff;
        #pragma unroll
        for (int ks = 0; ks < 2; ks++) {
            const int kkb = ks * 16 * 2;   // byte offset within row
            uint32_t a[2][4];
            #pragma unroll
            for (int m = 0; m < 2; m++)
                ldsm_x4(a[m], abase + m * 16 * ASTR * 2 + kkb);
            uint32_t b[8][2];
            #pragma unroll
            for (int p = 0; p < 4; p++) {
                uint32_t b4[4];
                ldsm_x4(b4, bbase + p * 16 * ASTR * 2 + kkb);
                b[2 * p][0] = b4[0];     b[2 * p][1] = b4[1];
                b[2 * p + 1][0] = b4[2]; b[2 * p + 1][1] = b4[3];
            }
            #pragma unroll
            for (int m = 0; m < 2; m++)
                #pragma unroll
                for (int j = 0; j < 8; j++)
                    mma_f16(acc[m][j], a[m], b[j]);
        }
        __syncthreads();
    }

    float bep_r[16], wv_r[16];
    #pragma unroll
    for (int j = 0; j < 8; j++) {
        int cc = n0 + warp_n * 64 + j * 8 + qc * 2;
        bep_r[j * 2] = b_ep[cc];     bep_r[j * 2 + 1] = b_ep[cc + 1];
        wv_r[j * 2]  = w_v[cc];      wv_r[j * 2 + 1]  = w_v[cc + 1];
    }

    #pragma unroll
    for (int g = 0; g < 4; g++) {
        int m = g >> 1;
        int lrr = warp_m * 32 + m * 16 + (g & 1) * 8 + qr;
        int r = row0 + lrr;
        int bb = r & 255;
        const float* hid = g_hidden_attn + (size_t)bb * HID + n0 + warp_n * 64;
        const int i0 = (g & 1) * 2;
        float p = 0.f;
        #pragma unroll
        for (int j = 0; j < 8; j++) {
            int cl = j * 8 + qc * 2;
            float v0 = acc[m][j][i0]     + bep_r[j * 2]     + hid[cl];
            float v1 = acc[m][j][i0 + 1] + bep_r[j * 2 + 1] + hid[cl + 1];
            p += tanh_fast(v0) * wv_r[j * 2] + tanh_fast(v1) * wv_r[j * 2 + 1];
        }
        p += __shfl_xor_sync(0xffffffffu, p, 1);
        p += __shfl_xor_sync(0xffffffffu, p, 2);
        if (qc == 0) {
            int t = r >> 8;
            g_scores_part[blockIdx.y * 4 + warp_n][bb * TSEQ + t] = p;
        }
    }
}

// ===== softmax over t =====
__global__ __launch_bounds__(256) void k_softmax(float* __restrict__ out_attn) {
    int b = blockIdx.x, tid = threadIdx.x;
    __shared__ float sw[TSEQ];
    __shared__ float red[256];

    float lm = -1e30f;
    for (int t = tid; t < TSEQ; t += 256) {
        float s = 0.f;
        #pragma unroll
        for (int q = 0; q < 8; q++) s += g_scores_part[q][b * TSEQ + t];
        sw[t] = s;
        lm = fmaxf(lm, s);
    }
    red[tid] = lm;
    __syncthreads();
    for (int off = 128; off > 0; off >>= 1) {
        if (tid < off) red[tid] = fmaxf(red[tid], red[tid + off]);
        __syncthreads();
    }
    float m = red[0];
    __syncthreads();
    float ls = 0.f;
    for (int t = tid; t < TSEQ; t += 256) {
        float e = __expf(sw[t] - m);
        sw[t] = e;
        ls += e;
    }
    red[tid] = ls;
    __syncthreads();
    for (int off = 128; off > 0; off >>= 1) {
        if (tid < off) red[tid] += red[tid + off];
        __syncthreads();
    }
    float inv = 1.f / red[0];
    __syncthreads();
    for (int t = tid; t < TSEQ; t += 256)
        out_attn[b * TSEQ + t] = sw[t] * inv;
}

// ===== context partials; grid (BATCH, 4) =====
__global__ __launch_bounds__(256) void k_context(
    const float* __restrict__ enc, const float* __restrict__ attn) {
    int b = blockIdx.x, ch = blockIdx.y, tid = threadIdx.x;
    __shared__ float sw[TCHUNK];
    for (int t = tid; t < TCHUNK; t += 256)
        sw[t] = attn[b * TSEQ + ch * TCHUNK + t];
    __syncthreads();
    float acc0 = 0.f, acc1 = 0.f;
    const float* ep = enc + (size_t)(ch * TCHUNK) * (BATCH * HID) + b * HID + tid;
    #pragma unroll 4
    for (int t = 0; t < TCHUNK; t++) {
        float w = sw[t];
        acc0 += ep[(size_t)t * (BATCH * HID)] * w;
        acc1 += ep[(size_t)t * (BATCH * HID) + 256] * w;
    }
    g_ctx_part[ch][b * HID + tid] = acc0;
    g_ctx_part[ch][b * HID + tid + 256] = acc1;
}

__global__ __launch_bounds__(256) void k_ctx_combine() {
    int idx = blockIdx.x * 256 + threadIdx.x;
    g_context[idx] = ((g_ctx_part[0][idx] + g_ctx_part[1][idx])
                    + g_ctx_part[2][idx]) + g_ctx_part[3][idx];
}

// ===== argmax + embed =====
__global__ __launch_bounds__(64) void k_argmax_embed(
    const float* __restrict__ in_char, const float* __restrict__ emb) {
    int b = blockIdx.x, tid = threadIdx.x;
    __shared__ int s_idx;
    if (tid < 32) {
        float bv = -1e30f; int bi = 0;
        for (int i = tid; i < VOCAB; i += 32) {
            float v = in_char[b * VOCAB + i];
            if (v > bv) { bv = v; bi = i; }
        }
        #pragma unroll
        for (int off = 16; off > 0; off >>= 1) {
            float ov = __shfl_down_sync(0xffffffffu, bv, off);
            int   oi = __shfl_down_sync(0xffffffffu, bi, off);
            if (ov > bv || (ov == bv && oi < bi)) { bv = ov; bi = oi; }
        }
        if (tid == 0) s_idx = bi;
    }
    __syncthreads();
    int t1 = s_idx;
    if (tid < EMBED) g_indec[b * INDEC_LD + tid] = emb[t1 * EMBED + tid];
    if (tid >= EMBED && tid < EMBED + 4)
        g_indec[b * INDEC_LD + 300 + (tid - EMBED)] = 0.f;
}

// ===== 64x64 tiled tail GEMM: C = A@B + bias =====
__global__ __launch_bounds__(256) void k_gemm64(
    const float* __restrict__ A, int lda,
    const float* __restrict__ B, int ldb,
    const float* __restrict__ bias,
    float* __restrict__ C, int ldc, int N, int K) {
    __shared__ float As[16][68];
    __shared__ float Bs[16][68];
    const int tid = threadIdx.x;
    const int row0 = blockIdx.x * 64, n0 = blockIdx.y * 64;
    const int tx = tid & 15, ty = tid >> 4;
    const int ar = tid >> 2, aseg = (tid & 3) * 4;
    const int brr = tid >> 4, bn = (tid & 15) * 4;

    float acc[4][4];
    #pragma unroll
    for (int i = 0; i < 4; i++)
        #pragma unroll
        for (int j = 0; j < 4; j++) acc[i][j] = 0.f;

    const int Kpad = (K + 15) & ~15;
    for (int k0 = 0; k0 < Kpad; k0 += 16) {
        float4 av = *(const float4*)(A + (size_t)(row0 + ar) * lda + k0 + aseg);
        As[aseg + 0][ar] = av.x;
        As[aseg + 1][ar] = av.y;
        As[aseg + 2][ar] = av.z;
        As[aseg + 3][ar] = av.w;
        #pragma unroll
        for (int i = 0; i < 4; i++) {
            int gk = k0 + brr, gn = n0 + bn + i;
            Bs[brr][bn + i] = (gk < K && gn < N) ? B[(size_t)gk * ldb + gn] : 0.f;
        }
        __syncthreads();
        #pragma unroll
        for (int k = 0; k < 16; k++) {
            float4 a4 = *(const float4*)&As[k][ty * 4];
            float4 b4 = *(const float4*)&Bs[k][tx * 4];
            float a[4] = {a4.x, a4.y, a4.z, a4.w};
            float b[4] = {b4.x, b4.y, b4.z, b4.w};
            #pragma unroll
            for (int i = 0; i < 4; i++)
                #pragma unroll
                for (int j = 0; j < 4; j++) acc[i][j] += a[i] * b[j];
        }
        __syncthreads();
    }

    #pragma unroll
    for (int i = 0; i < 4; i++) {
        int r = row0 + ty * 4 + i;
        #pragma unroll
        for (int j = 0; j < 4; j++) {
            int c = n0 + tx * 4 + j;
            if (c < N) C[(size_t)r * ldc + c] = acc[i][j] + bias[c];
        }
    }
}

// ===== GRU gates =====
__global__ __launch_bounds__(256) void k_gates(
    const float* __restrict__ hidden, float* __restrict__ out_newh) {
    int idx = blockIdx.x * 256 + threadIdx.x;
    int b = idx >> 9, j = idx & 511;
    const float* gi = g_gi + b * 3 * HID;
    const float* gh = g_gh + b * 3 * HID;
    float r = sigmoidf_(gi[j] + gh[j]);
    float z = sigmoidf_(gi[HID + j] + gh[HID + j]);
    float n = tanhf(gi[2 * HID + j] + r * gh[2 * HID + j]);
    float h = hidden[idx];
    out_newh[idx] = (1.f - z) * n + z * h;
}

// ===== output softmax =====
__global__ __launch_bounds__(128) void k_out_softmax(
    const float* __restrict__ newh, const float* __restrict__ W_out,
    const float* __restrict__ b_out, float* __restrict__ out_logits) {
    int b = blockIdx.x, tid = threadIdx.x;
    __shared__ float sh[HID];
    __shared__ float se[VOCAB];
    __shared__ float sred[2];
    #pragma unroll
    for (int i = 0; i < 4; i++) sh[tid + i * 128] = newh[b * HID + tid + i * 128];
    __syncthreads();
    if (tid < VOCAB) {
        float acc = b_out[tid];
        #pragma unroll 8
        for (int k = 0; k < HID; k++) acc += sh[k] * W_out[k * VOCAB + tid];
        se[tid] = acc;
    }
    __syncthreads();
    if (tid == 0) {
        float m = se[0];
        for (int i = 1; i < VOCAB; i++) m = fmaxf(m, se[i]);
        sred[0] = m;
    }
    __syncthreads();
    if (tid < VOCAB) se[tid] = __expf(se[tid] - sred[0]);
    __syncthreads();
    if (tid == 0) {
        float s = 0.f;
        for (int i = 0; i < VOCAB; i++) s += se[i];
        sred[1] = 1.f / s;
    }
    __syncthreads();
    if (tid < VOCAB) out_logits[b * VOCAB + tid] = se[tid] * sred[1];
}

// =============================== launcher ===============================
extern "C" void kernel_launch(void* const* d_in, const int* in_sizes, int n_in,
                              void* d_out, int out_size) {
    const float* in_char = (const float*)d_in[0];
    const float* hidden  = (const float*)d_in[1];
    const float* enc     = (const float*)d_in[2];
    const float* W_hp    = (const float*)d_in[3];
    const float* b_hp    = (const float*)d_in[4];
    const float* W_ep    = (const float*)d_in[5];
    const float* b_ep    = (const float*)d_in[6];
    const float* w_v     = (const float*)d_in[7];
    const float* W_cs    = (const float*)d_in[9];
    const float* b_cs    = (const float*)d_in[10];
    const float* emb     = (const float*)d_in[11];
    const float* W_ih    = (const float*)d_in[12];
    const float* b_ih    = (const float*)d_in[13];
    const float* W_hh    = (const float*)d_in[14];
    const float* b_hh    = (const float*)d_in[15];
    const float* W_out   = (const float*)d_in[16];
    const float* b_out   = (const float*)d_in[17];

    float* out = (float*)d_out;
    float* out_logits = out;
    float* out_newh   = out + BATCH * VOCAB;
    float* out_attn   = out + BATCH * VOCAB + BATCH * HID;

    float* p_indec; cudaGetSymbolAddress((void**)&p_indec, g_indec);
    float* p_gi;    cudaGetSymbolAddress((void**)&p_gi, g_gi);
    float* p_gh;    cudaGetSymbolAddress((void**)&p_gh, g_gh);
    float* p_ctx;   cudaGetSymbolAddress((void**)&p_ctx, g_context);
    float* p_hattn; cudaGetSymbolAddress((void**)&p_hattn, g_hidden_attn);

    cudaFuncSetAttribute(k_attn_gemm_mma,
                         cudaFuncAttributeMaxDynamicSharedMemorySize, SMEM_BYTES);

    // attention path
    k_convert_enc<<<(TSEQ * BATCH * HID) / (8 * 256), 256>>>(enc);
    k_transpose_wep<<<dim3(16, 16), 256>>>(W_ep);
    // hidden_attn = hidden @ W_hp + b_hp  (M=256,N=512,K=512)
    k_gemm64<<<dim3(4, 8), 256>>>(hidden, HID, W_hp, HID, b_hp,
                                  p_hattn, HID, HID, HID);
    k_attn_gemm_mma<<<dim3((TSEQ * BATCH) / 128, 2), 512, SMEM_BYTES>>>(b_ep, w_v);
    k_softmax<<<BATCH, 256>>>(out_attn);
    k_context<<<dim3(BATCH, 4), 256>>>(enc, out_attn);
    k_ctx_combine<<<(BATCH * HID) / 256, 256>>>();

    // decoder tail
    k_argmax_embed<<<BATCH, 64>>>(in_char, emb);
    k_gemm64<<<dim3(4, 4), 256>>>(p_ctx, HID, W_cs, 250, b_cs,
                                  p_indec + EMBED, INDEC_LD, 250, HID);
    k_gemm64<<<dim3(4, 24), 256>>>(p_indec, INDEC_LD, W_ih, 3 * HID, b_ih,
                                   p_gi, 3 * HID, 3 * HID, 300);
    k_gemm64<<<dim3(4, 24), 256>>>(hidden, HID, W_hh, 3 * HID, b_hh,
                                   p_gh, 3 * HID, 3 * HID, HID);
    k_gates<<<(BATCH * HID) / 256, 256>>>(hidden, out_newh);
    k_out_softmax<<<BATCH, 128>>>(out_newh, W_out, b_out, out_logits);
}

// round 14
// speedup vs baseline: 4.5287x; 1.0908x over previous
#include <cuda_runtime.h>
#include <cuda_fp16.h>
#include <math.h>
#include <cstdint>

#define HID 512
#define BATCH 256
#define TSEQ 600
#define VOCAB 83
#define EMBED 50
#define INDEC_LD 304
#define TCHUNK 150

// -------- scratch --------
__device__ float g_hidden_attn[BATCH * HID];
__device__ float g_scores_part[8][BATCH * TSEQ];
__device__ float g_context[BATCH * HID];
__device__ float g_ctx_part[4][BATCH * HID];
__device__ float g_indec[BATCH * INDEC_LD];
__device__ float g_gi[BATCH * 3 * HID];
__device__ float g_gh[BATCH * 3 * HID];
__device__ __half g_encH[(size_t)TSEQ * BATCH * HID];
__device__ __half g_WepH_T[HID * HID];

__device__ __forceinline__ float tanh_fast(float x) {
    float y; asm("tanh.approx.f32 %0, %1;" : "=f"(y) : "f"(x)); return y;
}
__device__ __forceinline__ float sigmoidf_(float x) {
    return 1.0f / (1.0f + __expf(-x));
}
__device__ __forceinline__ void mma_f16(float* c, const uint32_t* a, const uint32_t* b) {
    asm volatile(
        "mma.sync.aligned.m16n8k16.row.col.f32.f16.f16.f32 "
        "{%0,%1,%2,%3}, {%4,%5,%6,%7}, {%8,%9}, {%0,%1,%2,%3};"
        : "+f"(c[0]), "+f"(c[1]), "+f"(c[2]), "+f"(c[3])
        : "r"(a[0]), "r"(a[1]), "r"(a[2]), "r"(a[3]), "r"(b[0]), "r"(b[1]));
}
__device__ __forceinline__ void ldsm_x4(uint32_t* r, uint32_t addr) {
    asm volatile("ldmatrix.sync.aligned.m8n8.x4.shared.b16 {%0,%1,%2,%3}, [%4];"
        : "=r"(r[0]), "=r"(r[1]), "=r"(r[2]), "=r"(r[3]) : "r"(addr));
}
__device__ __forceinline__ void cp_async16(uint32_t dst, const void* src) {
    asm volatile("cp.async.cg.shared.global [%0], [%1], 16;" :: "r"(dst), "l"(src));
}
#define CP_COMMIT() asm volatile("cp.async.commit_group;" ::: "memory")
#define CP_WAIT(n)  asm volatile("cp.async.wait_group %0;" :: "n"(n) : "memory")

// ===== convert enc f32 -> f16 =====
__global__ __launch_bounds__(256) void k_convert_enc(const float* __restrict__ enc) {
    size_t i8 = ((size_t)blockIdx.x * 256 + threadIdx.x) * 8;
    float4 v0 = *(const float4*)(enc + i8);
    float4 v1 = *(const float4*)(enc + i8 + 4);
    __half2 h[4];
    h[0] = __halves2half2(__float2half_rn(v0.x), __float2half_rn(v0.y));
    h[1] = __halves2half2(__float2half_rn(v0.z), __float2half_rn(v0.w));
    h[2] = __halves2half2(__float2half_rn(v1.x), __float2half_rn(v1.y));
    h[3] = __halves2half2(__float2half_rn(v1.z), __float2half_rn(v1.w));
    const uint32_t* hu = (const uint32_t*)h;
    *(uint2*)(g_encH + i8)     = make_uint2(hu[0], hu[1]);
    *(uint2*)(g_encH + i8 + 4) = make_uint2(hu[2], hu[3]);
}

// ===== transpose W_ep -> fp16 =====
__global__ __launch_bounds__(256) void k_transpose_wep(const float* __restrict__ W) {
    __shared__ float t[32][33];
    int bx = blockIdx.x * 32, by = blockIdx.y * 32;
    int x = threadIdx.x & 31, y = threadIdx.x >> 5;
    #pragma unroll
    for (int i = 0; i < 32; i += 8)
        t[y + i][x] = W[(size_t)(by + y + i) * HID + bx + x];
    __syncthreads();
    #pragma unroll
    for (int i = 0; i < 32; i += 8)
        g_WepH_T[(size_t)(bx + y + i) * HID + by + x] = __float2half_rn(t[x][y + i]);
}

// ===== K_B: fp16 m16n8k16 GEMM, K=64 chunks, cp.async + ldmatrix =====
#define ASTR 72                       // 64 data + 8 pad halves
#define A_BUF_H (128 * ASTR)
#define B_BUF_H (256 * ASTR)
#define SMEM_BYTES ((A_BUF_H + B_BUF_H) * 2 * 2)

__global__ __launch_bounds__(512, 1) void k_attn_gemm_mma(
    const float* __restrict__ b_ep, const float* __restrict__ w_v) {
    extern __shared__ __half sm[];
    __half* As = sm;                      // [2][128][72]
    __half* Bs = sm + 2 * A_BUF_H;        // [2][256][72]

    const int tid = threadIdx.x;
    const int lane = tid & 31, wid = tid >> 5;
    const int warp_m = wid & 3, warp_n = wid >> 2;
    const int row0 = blockIdx.x * 128, n0 = blockIdx.y * 256;
    const int qr = lane >> 2, qc = lane & 3;

    const __half* Ag = g_encH + (size_t)row0 * HID;
    const __half* Bg = g_WepH_T + (size_t)n0 * HID;

    const uint32_t sA = (uint32_t)__cvta_generic_to_shared(As);
    const uint32_t sB = (uint32_t)__cvta_generic_to_shared(Bs);

    // ldmatrix lane address bases (bytes)
    const int rg = lane & 7;
    const uint32_t aoff = ((warp_m * 32 + ((lane >> 3) & 1) * 8 + rg) * ASTR
                          + ((lane >> 4) & 1) * 8) * 2;
    const uint32_t boff = ((warp_n * 64 + ((lane >> 4) & 1) * 8 + rg) * ASTR
                          + ((lane >> 3) & 1) * 8) * 2;

    // load tasks: row = e>>3, seg = (e&7)*8 halves
    const int lr = tid >> 3, lseg = (tid & 7) * 8;
    {
        #pragma unroll
        for (int i = 0; i < 2; i++) {
            int r = lr + i * 64;
            cp_async16(sA + (r * ASTR + lseg) * 2, Ag + (size_t)r * HID + lseg);
        }
        #pragma unroll
        for (int i = 0; i < 4; i++) {
            int r = lr + i * 64;
            cp_async16(sB + (r * ASTR + lseg) * 2, Bg + (size_t)r * HID + lseg);
        }
        CP_COMMIT();
    }

    float acc[2][8][4];
    #pragma unroll
    for (int m = 0; m < 2; m++)
        #pragma unroll
        for (int j = 0; j < 8; j++)
            #pragma unroll
            for (int i = 0; i < 4; i++) acc[m][j][i] = 0.f;

    for (int c = 0; c < 8; c++) {
        const int buf = c & 1;
        if (c < 7) {
            const int nb = (c + 1) & 1;
            const int k0 = (c + 1) * 64;
            #pragma unroll
            for (int i = 0; i < 2; i++) {
                int r = lr + i * 64;
                cp_async16(sA + (nb * A_BUF_H + r * ASTR + lseg) * 2,
                           Ag + (size_t)r * HID + k0 + lseg);
            }
            #pragma unroll
            for (int i = 0; i < 4; i++) {
                int r = lr + i * 64;
                cp_async16(sB + (nb * B_BUF_H + r * ASTR + lseg) * 2,
                           Bg + (size_t)r * HID + k0 + lseg);
            }
            CP_COMMIT();
            CP_WAIT(1);
        } else {
            CP_WAIT(0);
        }
        __syncthreads();

        const uint32_t abase = sA + buf * A_BUF_H * 2 + aoff;
        const uint32_t bbase = sB + buf * B_BUF_H * 2 + boff;
        #pragma unroll
        for (int ks = 0; ks < 4; ks++) {
            const int kkb = ks * 16 * 2;
            uint32_t a[2][4];
            #pragma unroll
            for (int m = 0; m < 2; m++)
                ldsm_x4(a[m], abase + m * 16 * ASTR * 2 + kkb);
            uint32_t b[8][2];
            #pragma unroll
            for (int p = 0; p < 4; p++) {
                uint32_t b4[4];
                ldsm_x4(b4, bbase + p * 16 * ASTR * 2 + kkb);
                b[2 * p][0] = b4[0];     b[2 * p][1] = b4[1];
                b[2 * p + 1][0] = b4[2]; b[2 * p + 1][1] = b4[3];
            }
            #pragma unroll
            for (int m = 0; m < 2; m++)
                #pragma unroll
                for (int j = 0; j < 8; j++)
                    mma_f16(acc[m][j], a[m], b[j]);
        }
        __syncthreads();
    }

    float bep_r[16], wv_r[16];
    #pragma unroll
    for (int j = 0; j < 8; j++) {
        int cc = n0 + warp_n * 64 + j * 8 + qc * 2;
        bep_r[j * 2] = b_ep[cc];     bep_r[j * 2 + 1] = b_ep[cc + 1];
        wv_r[j * 2]  = w_v[cc];      wv_r[j * 2 + 1]  = w_v[cc + 1];
    }

    #pragma unroll
    for (int g = 0; g < 4; g++) {
        int m = g >> 1;
        int lrr = warp_m * 32 + m * 16 + (g & 1) * 8 + qr;
        int r = row0 + lrr;
        int bb = r & 255;
        const float* hid = g_hidden_attn + (size_t)bb * HID + n0 + warp_n * 64;
        const int i0 = (g & 1) * 2;
        float p = 0.f;
        #pragma unroll
        for (int j = 0; j < 8; j++) {
            int cl = j * 8 + qc * 2;
            float v0 = acc[m][j][i0]     + bep_r[j * 2]     + hid[cl];
            float v1 = acc[m][j][i0 + 1] + bep_r[j * 2 + 1] + hid[cl + 1];
            p += tanh_fast(v0) * wv_r[j * 2] + tanh_fast(v1) * wv_r[j * 2 + 1];
        }
        p += __shfl_xor_sync(0xffffffffu, p, 1);
        p += __shfl_xor_sync(0xffffffffu, p, 2);
        if (qc == 0) {
            int t = r >> 8;
            g_scores_part[blockIdx.y * 4 + warp_n][bb * TSEQ + t] = p;
        }
    }
}

// ===== softmax over t =====
__global__ __launch_bounds__(256) void k_softmax(float* __restrict__ out_attn) {
    int b = blockIdx.x, tid = threadIdx.x;
    __shared__ float sw[TSEQ];
    __shared__ float red[256];

    float lm = -1e30f;
    for (int t = tid; t < TSEQ; t += 256) {
        float s = 0.f;
        #pragma unroll
        for (int q = 0; q < 8; q++) s += g_scores_part[q][b * TSEQ + t];
        sw[t] = s;
        lm = fmaxf(lm, s);
    }
    red[tid] = lm;
    __syncthreads();
    for (int off = 128; off > 0; off >>= 1) {
        if (tid < off) red[tid] = fmaxf(red[tid], red[tid + off]);
        __syncthreads();
    }
    float m = red[0];
    __syncthreads();
    float ls = 0.f;
    for (int t = tid; t < TSEQ; t += 256) {
        float e = __expf(sw[t] - m);
        sw[t] = e;
        ls += e;
    }
    red[tid] = ls;
    __syncthreads();
    for (int off = 128; off > 0; off >>= 1) {
        if (tid < off) red[tid] += red[tid + off];
        __syncthreads();
    }
    float inv = 1.f / red[0];
    __syncthreads();
    for (int t = tid; t < TSEQ; t += 256)
        out_attn[b * TSEQ + t] = sw[t] * inv;
}

// ===== context partials from fp16 enc; grid (BATCH, 4) =====
__global__ __launch_bounds__(256) void k_context(const float* __restrict__ attn) {
    int b = blockIdx.x, ch = blockIdx.y, tid = threadIdx.x;
    __shared__ float sw[TCHUNK];
    for (int t = tid; t < TCHUNK; t += 256)
        sw[t] = attn[b * TSEQ + ch * TCHUNK + t];
    __syncthreads();
    float acc0 = 0.f, acc1 = 0.f;
    // half2 columns: thread handles cols (2*tid, 2*tid+1)
    const __half2* ep = (const __half2*)(g_encH + (size_t)(ch * TCHUNK) * (BATCH * HID)
                                         + (size_t)b * HID) + tid;
    #pragma unroll 4
    for (int t = 0; t < TCHUNK; t++) {
        float w = sw[t];
        float2 v = __half22float2(ep[(size_t)t * (BATCH * HID / 2)]);
        acc0 += v.x * w;
        acc1 += v.y * w;
    }
    g_ctx_part[ch][b * HID + 2 * tid]     = acc0;
    g_ctx_part[ch][b * HID + 2 * tid + 1] = acc1;
}

__global__ __launch_bounds__(256) void k_ctx_combine() {
    int idx = blockIdx.x * 256 + threadIdx.x;
    g_context[idx] = ((g_ctx_part[0][idx] + g_ctx_part[1][idx])
                    + g_ctx_part[2][idx]) + g_ctx_part[3][idx];
}

// ===== argmax + embed =====
__global__ __launch_bounds__(64) void k_argmax_embed(
    const float* __restrict__ in_char, const float* __restrict__ emb) {
    int b = blockIdx.x, tid = threadIdx.x;
    __shared__ int s_idx;
    if (tid < 32) {
        float bv = -1e30f; int bi = 0;
        for (int i = tid; i < VOCAB; i += 32) {
            float v = in_char[b * VOCAB + i];
            if (v > bv) { bv = v; bi = i; }
        }
        #pragma unroll
        for (int off = 16; off > 0; off >>= 1) {
            float ov = __shfl_down_sync(0xffffffffu, bv, off);
            int   oi = __shfl_down_sync(0xffffffffu, bi, off);
            if (ov > bv || (ov == bv && oi < bi)) { bv = ov; bi = oi; }
        }
        if (tid == 0) s_idx = bi;
    }
    __syncthreads();
    int t1 = s_idx;
    if (tid < EMBED) g_indec[b * INDEC_LD + tid] = emb[t1 * EMBED + tid];
    if (tid >= EMBED && tid < EMBED + 4)
        g_indec[b * INDEC_LD + 300 + (tid - EMBED)] = 0.f;
}

// ===== 64x64 tiled tail GEMM =====
__global__ __launch_bounds__(256) void k_gemm64(
    const float* __restrict__ A, int lda,
    const float* __restrict__ B, int ldb,
    const float* __restrict__ bias,
    float* __restrict__ C, int ldc, int N, int K) {
    __shared__ float As[16][68];
    __shared__ float Bs[16][68];
    const int tid = threadIdx.x;
    const int row0 = blockIdx.x * 64, n0 = blockIdx.y * 64;
    const int tx = tid & 15, ty = tid >> 4;
    const int ar = tid >> 2, aseg = (tid & 3) * 4;
    const int brr = tid >> 4, bn = (tid & 15) * 4;

    float acc[4][4];
    #pragma unroll
    for (int i = 0; i < 4; i++)
        #pragma unroll
        for (int j = 0; j < 4; j++) acc[i][j] = 0.f;

    const int Kpad = (K + 15) & ~15;
    for (int k0 = 0; k0 < Kpad; k0 += 16) {
        float4 av = *(const float4*)(A + (size_t)(row0 + ar) * lda + k0 + aseg);
        As[aseg + 0][ar] = av.x;
        As[aseg + 1][ar] = av.y;
        As[aseg + 2][ar] = av.z;
        As[aseg + 3][ar] = av.w;
        #pragma unroll
        for (int i = 0; i < 4; i++) {
            int gk = k0 + brr, gn = n0 + bn + i;
            Bs[brr][bn + i] = (gk < K && gn < N) ? B[(size_t)gk * ldb + gn] : 0.f;
        }
        __syncthreads();
        #pragma unroll
        for (int k = 0; k < 16; k++) {
            float4 a4 = *(const float4*)&As[k][ty * 4];
            float4 b4 = *(const float4*)&Bs[k][tx * 4];
            float a[4] = {a4.x, a4.y, a4.z, a4.w};
            float b[4] = {b4.x, b4.y, b4.z, b4.w};
            #pragma unroll
            for (int i = 0; i < 4; i++)
                #pragma unroll
                for (int j = 0; j < 4; j++) acc[i][j] += a[i] * b[j];
        }
        __syncthreads();
    }

    #pragma unroll
    for (int i = 0; i < 4; i++) {
        int r = row0 + ty * 4 + i;
        #pragma unroll
        for (int j = 0; j < 4; j++) {
            int c = n0 + tx * 4 + j;
            if (c < N) C[(size_t)r * ldc + c] = acc[i][j] + bias[c];
        }
    }
}

// ===== GRU gates =====
__global__ __launch_bounds__(256) void k_gates(
    const float* __restrict__ hidden, float* __restrict__ out_newh) {
    int idx = blockIdx.x * 256 + threadIdx.x;
    int b = idx >> 9, j = idx & 511;
    const float* gi = g_gi + b * 3 * HID;
    const float* gh = g_gh + b * 3 * HID;
    float r = sigmoidf_(gi[j] + gh[j]);
    float z = sigmoidf_(gi[HID + j] + gh[HID + j]);
    float n = tanhf(gi[2 * HID + j] + r * gh[2 * HID + j]);
    float h = hidden[idx];
    out_newh[idx] = (1.f - z) * n + z * h;
}

// ===== output softmax =====
__global__ __launch_bounds__(128) void k_out_softmax(
    const float* __restrict__ newh, const float* __restrict__ W_out,
    const float* __restrict__ b_out, float* __restrict__ out_logits) {
    int b = blockIdx.x, tid = threadIdx.x;
    __shared__ float sh[HID];
    __shared__ float se[VOCAB];
    __shared__ float sred[2];
    #pragma unroll
    for (int i = 0; i < 4; i++) sh[tid + i * 128] = newh[b * HID + tid + i * 128];
    __syncthreads();
    if (tid < VOCAB) {
        float acc = b_out[tid];
        #pragma unroll 8
        for (int k = 0; k < HID; k++) acc += sh[k] * W_out[k * VOCAB + tid];
        se[tid] = acc;
    }
    __syncthreads();
    if (tid == 0) {
        float m = se[0];
        for (int i = 1; i < VOCAB; i++) m = fmaxf(m, se[i]);
        sred[0] = m;
    }
    __syncthreads();
    if (tid < VOCAB) se[tid] = __expf(se[tid] - sred[0]);
    __syncthreads();
    if (tid == 0) {
        float s = 0.f;
        for (int i = 0; i < VOCAB; i++) s += se[i];
        sred[1] = 1.f / s;
    }
    __syncthreads();
    if (tid < VOCAB) out_logits[b * VOCAB + tid] = se[tid] * sred[1];
}

// =============================== launcher ===============================
extern "C" void kernel_launch(void* const* d_in, const int* in_sizes, int n_in,
                              void* d_out, int out_size) {
    const float* in_char = (const float*)d_in[0];
    const float* hidden  = (const float*)d_in[1];
    const float* enc     = (const float*)d_in[2];
    const float* W_hp    = (const float*)d_in[3];
    const float* b_hp    = (const float*)d_in[4];
    const float* W_ep    = (const float*)d_in[5];
    const float* b_ep    = (const float*)d_in[6];
    const float* w_v     = (const float*)d_in[7];
    const float* W_cs    = (const float*)d_in[9];
    const float* b_cs    = (const float*)d_in[10];
    const float* emb     = (const float*)d_in[11];
    const float* W_ih    = (const float*)d_in[12];
    const float* b_ih    = (const float*)d_in[13];
    const float* W_hh    = (const float*)d_in[14];
    const float* b_hh    = (const float*)d_in[15];
    const float* W_out   = (const float*)d_in[16];
    const float* b_out   = (const float*)d_in[17];

    float* out = (float*)d_out;
    float* out_logits = out;
    float* out_newh   = out + BATCH * VOCAB;
    float* out_attn   = out + BATCH * VOCAB + BATCH * HID;

    float* p_indec; cudaGetSymbolAddress((void**)&p_indec, g_indec);
    float* p_gi;    cudaGetSymbolAddress((void**)&p_gi, g_gi);
    float* p_gh;    cudaGetSymbolAddress((void**)&p_gh, g_gh);
    float* p_ctx;   cudaGetSymbolAddress((void**)&p_ctx, g_context);
    float* p_hattn; cudaGetSymbolAddress((void**)&p_hattn, g_hidden_attn);

    cudaFuncSetAttribute(k_attn_gemm_mma,
                         cudaFuncAttributeMaxDynamicSharedMemorySize, SMEM_BYTES);

    // attention path
    k_convert_enc<<<(TSEQ * BATCH * HID) / (8 * 256), 256>>>(enc);
    k_transpose_wep<<<dim3(16, 16), 256>>>(W_ep);
    k_gemm64<<<dim3(4, 8), 256>>>(hidden, HID, W_hp, HID, b_hp,
                                  p_hattn, HID, HID, HID);
    k_attn_gemm_mma<<<dim3((TSEQ * BATCH) / 128, 2), 512, SMEM_BYTES>>>(b_ep, w_v);
    k_softmax<<<BATCH, 256>>>(out_attn);
    k_context<<<dim3(BATCH, 4), 256>>>(out_attn);
    k_ctx_combine<<<(BATCH * HID) / 256, 256>>>();

    // decoder tail
    k_argmax_embed<<<BATCH, 64>>>(in_char, emb);
    k_gemm64<<<dim3(4, 4), 256>>>(p_ctx, HID, W_cs, 250, b_cs,
                                  p_indec + EMBED, INDEC_LD, 250, HID);
    k_gemm64<<<dim3(4, 24), 256>>>(p_indec, INDEC_LD, W_ih, 3 * HID, b_ih,
                                   p_gi, 3 * HID, 3 * HID, 300);
    k_gemm64<<<dim3(4, 24), 256>>>(hidden, HID, W_hh, 3 * HID, b_hh,
                                   p_gh, 3 * HID, 3 * HID, HID);
    k_gates<<<(BATCH * HID) / 256, 256>>>(hidden, out_newh);
    k_out_softmax<<<BATCH, 128>>>(out_newh, W_out, b_out, out_logits);
}

// round 15
// speedup vs baseline: 5.0455x; 1.1141x over previous
#include <cuda_runtime.h>
#include <cuda_fp16.h>
#include <math.h>
#include <cstdint>

#define HID 512
#define BATCH 256
#define TSEQ 600
#define VOCAB 83
#define EMBED 50
#define INDEC_LD 304
#define TCHUNK 150

// -------- scratch --------
__device__ float g_hidden_attn[BATCH * HID];
__device__ float g_scores_part[8][BATCH * TSEQ];
__device__ float g_context[BATCH * HID];
__device__ float g_ctx_part[4][BATCH * HID];
__device__ float g_indec[BATCH * INDEC_LD];
__device__ float g_gi[BATCH * 3 * HID];
__device__ float g_gh[BATCH * 3 * HID];
__device__ __half g_encH[(size_t)TSEQ * BATCH * HID];
__device__ __half g_WepH_T[HID * HID];

__device__ __forceinline__ float tanh_fast(float x) {
    float y; asm("tanh.approx.f32 %0, %1;" : "=f"(y) : "f"(x)); return y;
}
__device__ __forceinline__ float sigmoidf_(float x) {
    return 1.0f / (1.0f + __expf(-x));
}
__device__ __forceinline__ void mma_f16(float* c, const uint32_t* a, const uint32_t* b) {
    asm volatile(
        "mma.sync.aligned.m16n8k16.row.col.f32.f16.f16.f32 "
        "{%0,%1,%2,%3}, {%4,%5,%6,%7}, {%8,%9}, {%0,%1,%2,%3};"
        : "+f"(c[0]), "+f"(c[1]), "+f"(c[2]), "+f"(c[3])
        : "r"(a[0]), "r"(a[1]), "r"(a[2]), "r"(a[3]), "r"(b[0]), "r"(b[1]));
}
__device__ __forceinline__ void ldsm_x4(uint32_t* r, uint32_t addr) {
    asm volatile("ldmatrix.sync.aligned.m8n8.x4.shared.b16 {%0,%1,%2,%3}, [%4];"
        : "=r"(r[0]), "=r"(r[1]), "=r"(r[2]), "=r"(r[3]) : "r"(addr));
}
__device__ __forceinline__ void cp_async16(uint32_t dst, const void* src) {
    asm volatile("cp.async.cg.shared.global [%0], [%1], 16;" :: "r"(dst), "l"(src));
}
#define CP_COMMIT() asm volatile("cp.async.commit_group;" ::: "memory")
#define CP_WAIT(n)  asm volatile("cp.async.wait_group %0;" :: "n"(n) : "memory")

// ===== convert enc f32 -> f16 =====
__global__ __launch_bounds__(256) void k_convert_enc(const float* __restrict__ enc) {
    size_t i8 = ((size_t)blockIdx.x * 256 + threadIdx.x) * 8;
    float4 v0 = *(const float4*)(enc + i8);
    float4 v1 = *(const float4*)(enc + i8 + 4);
    __half2 h[4];
    h[0] = __halves2half2(__float2half_rn(v0.x), __float2half_rn(v0.y));
    h[1] = __halves2half2(__float2half_rn(v0.z), __float2half_rn(v0.w));
    h[2] = __halves2half2(__float2half_rn(v1.x), __float2half_rn(v1.y));
    h[3] = __halves2half2(__float2half_rn(v1.z), __float2half_rn(v1.w));
    const uint32_t* hu = (const uint32_t*)h;
    *(uint2*)(g_encH + i8)     = make_uint2(hu[0], hu[1]);
    *(uint2*)(g_encH + i8 + 4) = make_uint2(hu[2], hu[3]);
}

// ===== transpose W_ep -> fp16 =====
__global__ __launch_bounds__(256) void k_transpose_wep(const float* __restrict__ W) {
    __shared__ float t[32][33];
    int bx = blockIdx.x * 32, by = blockIdx.y * 32;
    int x = threadIdx.x & 31, y = threadIdx.x >> 5;
    #pragma unroll
    for (int i = 0; i < 32; i += 8)
        t[y + i][x] = W[(size_t)(by + y + i) * HID + bx + x];
    __syncthreads();
    #pragma unroll
    for (int i = 0; i < 32; i += 8)
        g_WepH_T[(size_t)(bx + y + i) * HID + by + x] = __float2half_rn(t[x][y + i]);
}

// ===== K_B: fp16 m16n8k16 GEMM, CTA 128x128, 2 CTAs/SM =====
#define ASTR 72                       // 64 data + 8 pad halves
#define A_BUF_H (128 * ASTR)
#define B_BUF_H (128 * ASTR)
#define SMEM_BYTES ((A_BUF_H + B_BUF_H) * 2 * 2)

__global__ __launch_bounds__(256, 2) void k_attn_gemm_mma(
    const float* __restrict__ b_ep, const float* __restrict__ w_v) {
    extern __shared__ __half sm[];
    __half* As = sm;                      // [2][128][72]
    __half* Bs = sm + 2 * A_BUF_H;        // [2][128][72]

    const int tid = threadIdx.x;
    const int lane = tid & 31, wid = tid >> 5;
    const int warp_m = wid & 3, warp_n = wid >> 2;   // 4 x 2
    const int row0 = blockIdx.x * 128, n0 = blockIdx.y * 128;
    const int qr = lane >> 2, qc = lane & 3;

    const __half* Ag = g_encH + (size_t)row0 * HID;
    const __half* Bg = g_WepH_T + (size_t)n0 * HID;

    const uint32_t sA = (uint32_t)__cvta_generic_to_shared(As);
    const uint32_t sB = (uint32_t)__cvta_generic_to_shared(Bs);

    // ldmatrix lane address bases (bytes)
    const int rg = lane & 7;
    const uint32_t aoff = ((warp_m * 32 + ((lane >> 3) & 1) * 8 + rg) * ASTR
                          + ((lane >> 4) & 1) * 8) * 2;
    const uint32_t boff = ((warp_n * 64 + ((lane >> 4) & 1) * 8 + rg) * ASTR
                          + ((lane >> 3) & 1) * 8) * 2;

    // load tasks: 32 rows x 8 segs per i-step; 4 i-steps each for A and B
    const int lr = tid >> 3, lseg = (tid & 7) * 8;
    {
        #pragma unroll
        for (int i = 0; i < 4; i++) {
            int r = lr + i * 32;
            cp_async16(sA + (r * ASTR + lseg) * 2, Ag + (size_t)r * HID + lseg);
            cp_async16(sB + (r * ASTR + lseg) * 2, Bg + (size_t)r * HID + lseg);
        }
        CP_COMMIT();
    }

    float acc[2][8][4];
    #pragma unroll
    for (int m = 0; m < 2; m++)
        #pragma unroll
        for (int j = 0; j < 8; j++)
            #pragma unroll
            for (int i = 0; i < 4; i++) acc[m][j][i] = 0.f;

    for (int c = 0; c < 8; c++) {
        const int buf = c & 1;
        if (c < 7) {
            const int nb = (c + 1) & 1;
            const int k0 = (c + 1) * 64;
            #pragma unroll
            for (int i = 0; i < 4; i++) {
                int r = lr + i * 32;
                cp_async16(sA + (nb * A_BUF_H + r * ASTR + lseg) * 2,
                           Ag + (size_t)r * HID + k0 + lseg);
                cp_async16(sB + (nb * B_BUF_H + r * ASTR + lseg) * 2,
                           Bg + (size_t)r * HID + k0 + lseg);
            }
            CP_COMMIT();
            CP_WAIT(1);
        } else {
            CP_WAIT(0);
        }
        __syncthreads();

        const uint32_t abase = sA + buf * A_BUF_H * 2 + aoff;
        const uint32_t bbase = sB + buf * B_BUF_H * 2 + boff;
        #pragma unroll
        for (int ks = 0; ks < 4; ks++) {
            const int kkb = ks * 16 * 2;
            uint32_t a[2][4];
            #pragma unroll
            for (int m = 0; m < 2; m++)
                ldsm_x4(a[m], abase + m * 16 * ASTR * 2 + kkb);
            uint32_t b[8][2];
            #pragma unroll
            for (int p = 0; p < 4; p++) {
                uint32_t b4[4];
                ldsm_x4(b4, bbase + p * 16 * ASTR * 2 + kkb);
                b[2 * p][0] = b4[0];     b[2 * p][1] = b4[1];
                b[2 * p + 1][0] = b4[2]; b[2 * p + 1][1] = b4[3];
            }
            #pragma unroll
            for (int m = 0; m < 2; m++)
                #pragma unroll
                for (int j = 0; j < 8; j++)
                    mma_f16(acc[m][j], a[m], b[j]);
        }
        __syncthreads();
    }

    float bep_r[16], wv_r[16];
    #pragma unroll
    for (int j = 0; j < 8; j++) {
        int cc = n0 + warp_n * 64 + j * 8 + qc * 2;
        bep_r[j * 2] = b_ep[cc];     bep_r[j * 2 + 1] = b_ep[cc + 1];
        wv_r[j * 2]  = w_v[cc];      wv_r[j * 2 + 1]  = w_v[cc + 1];
    }

    #pragma unroll
    for (int g = 0; g < 4; g++) {
        int m = g >> 1;
        int lrr = warp_m * 32 + m * 16 + (g & 1) * 8 + qr;
        int r = row0 + lrr;
        int bb = r & 255;
        const float* hid = g_hidden_attn + (size_t)bb * HID + n0 + warp_n * 64;
        const int i0 = (g & 1) * 2;
        float p = 0.f;
        #pragma unroll
        for (int j = 0; j < 8; j++) {
            int cl = j * 8 + qc * 2;
            float v0 = acc[m][j][i0]     + bep_r[j * 2]     + hid[cl];
            float v1 = acc[m][j][i0 + 1] + bep_r[j * 2 + 1] + hid[cl + 1];
            p += tanh_fast(v0) * wv_r[j * 2] + tanh_fast(v1) * wv_r[j * 2 + 1];
        }
        p += __shfl_xor_sync(0xffffffffu, p, 1);
        p += __shfl_xor_sync(0xffffffffu, p, 2);
        if (qc == 0) {
            int t = r >> 8;
            g_scores_part[blockIdx.y * 2 + warp_n][bb * TSEQ + t] = p;
        }
    }
}

// ===== softmax over t =====
__global__ __launch_bounds__(256) void k_softmax(float* __restrict__ out_attn) {
    int b = blockIdx.x, tid = threadIdx.x;
    __shared__ float sw[TSEQ];
    __shared__ float red[256];

    float lm = -1e30f;
    for (int t = tid; t < TSEQ; t += 256) {
        float s = 0.f;
        #pragma unroll
        for (int q = 0; q < 8; q++) s += g_scores_part[q][b * TSEQ + t];
        sw[t] = s;
        lm = fmaxf(lm, s);
    }
    red[tid] = lm;
    __syncthreads();
    for (int off = 128; off > 0; off >>= 1) {
        if (tid < off) red[tid] = fmaxf(red[tid], red[tid + off]);
        __syncthreads();
    }
    float m = red[0];
    __syncthreads();
    float ls = 0.f;
    for (int t = tid; t < TSEQ; t += 256) {
        float e = __expf(sw[t] - m);
        sw[t] = e;
        ls += e;
    }
    red[tid] = ls;
    __syncthreads();
    for (int off = 128; off > 0; off >>= 1) {
        if (tid < off) red[tid] += red[tid + off];
        __syncthreads();
    }
    float inv = 1.f / red[0];
    __syncthreads();
    for (int t = tid; t < TSEQ; t += 256)
        out_attn[b * TSEQ + t] = sw[t] * inv;
}

// ===== context partials from fp16 enc; grid (BATCH, 4) =====
__global__ __launch_bounds__(256) void k_context(const float* __restrict__ attn) {
    int b = blockIdx.x, ch = blockIdx.y, tid = threadIdx.x;
    __shared__ float sw[TCHUNK];
    for (int t = tid; t < TCHUNK; t += 256)
        sw[t] = attn[b * TSEQ + ch * TCHUNK + t];
    __syncthreads();
    float acc0 = 0.f, acc1 = 0.f;
    const __half2* ep = (const __half2*)(g_encH + (size_t)(ch * TCHUNK) * (BATCH * HID)
                                         + (size_t)b * HID) + tid;
    #pragma unroll 4
    for (int t = 0; t < TCHUNK; t++) {
        float w = sw[t];
        float2 v = __half22float2(ep[(size_t)t * (BATCH * HID / 2)]);
        acc0 += v.x * w;
        acc1 += v.y * w;
    }
    g_ctx_part[ch][b * HID + 2 * tid]     = acc0;
    g_ctx_part[ch][b * HID + 2 * tid + 1] = acc1;
}

__global__ __launch_bounds__(256) void k_ctx_combine() {
    int idx = blockIdx.x * 256 + threadIdx.x;
    g_context[idx] = ((g_ctx_part[0][idx] + g_ctx_part[1][idx])
                    + g_ctx_part[2][idx]) + g_ctx_part[3][idx];
}

// ===== argmax + embed =====
__global__ __launch_bounds__(64) void k_argmax_embed(
    const float* __restrict__ in_char, const float* __restrict__ emb) {
    int b = blockIdx.x, tid = threadIdx.x;
    __shared__ int s_idx;
    if (tid < 32) {
        float bv = -1e30f; int bi = 0;
        for (int i = tid; i < VOCAB; i += 32) {
            float v = in_char[b * VOCAB + i];
            if (v > bv) { bv = v; bi = i; }
        }
        #pragma unroll
        for (int off = 16; off > 0; off >>= 1) {
            float ov = __shfl_down_sync(0xffffffffu, bv, off);
            int   oi = __shfl_down_sync(0xffffffffu, bi, off);
            if (ov > bv || (ov == bv && oi < bi)) { bv = ov; bi = oi; }
        }
        if (tid == 0) s_idx = bi;
    }
    __syncthreads();
    int t1 = s_idx;
    if (tid < EMBED) g_indec[b * INDEC_LD + tid] = emb[t1 * EMBED + tid];
    if (tid >= EMBED && tid < EMBED + 4)
        g_indec[b * INDEC_LD + 300 + (tid - EMBED)] = 0.f;
}

// ===== 64x64 tiled tail GEMM =====
__global__ __launch_bounds__(256) void k_gemm64(
    const float* __restrict__ A, int lda,
    const float* __restrict__ B, int ldb,
    const float* __restrict__ bias,
    float* __restrict__ C, int ldc, int N, int K) {
    __shared__ float As[16][68];
    __shared__ float Bs[16][68];
    const int tid = threadIdx.x;
    const int row0 = blockIdx.x * 64, n0 = blockIdx.y * 64;
    const int tx = tid & 15, ty = tid >> 4;
    const int ar = tid >> 2, aseg = (tid & 3) * 4;
    const int brr = tid >> 4, bn = (tid & 15) * 4;

    float acc[4][4];
    #pragma unroll
    for (int i = 0; i < 4; i++)
        #pragma unroll
        for (int j = 0; j < 4; j++) acc[i][j] = 0.f;

    const int Kpad = (K + 15) & ~15;
    for (int k0 = 0; k0 < Kpad; k0 += 16) {
        float4 av = *(const float4*)(A + (size_t)(row0 + ar) * lda + k0 + aseg);
        As[aseg + 0][ar] = av.x;
        As[aseg + 1][ar] = av.y;
        As[aseg + 2][ar] = av.z;
        As[aseg + 3][ar] = av.w;
        #pragma unroll
        for (int i = 0; i < 4; i++) {
            int gk = k0 + brr, gn = n0 + bn + i;
            Bs[brr][bn + i] = (gk < K && gn < N) ? B[(size_t)gk * ldb + gn] : 0.f;
        }
        __syncthreads();
        #pragma unroll
        for (int k = 0; k < 16; k++) {
            float4 a4 = *(const float4*)&As[k][ty * 4];
            float4 b4 = *(const float4*)&Bs[k][tx * 4];
            float a[4] = {a4.x, a4.y, a4.z, a4.w};
            float b[4] = {b4.x, b4.y, b4.z, b4.w};
            #pragma unroll
            for (int i = 0; i < 4; i++)
                #pragma unroll
                for (int j = 0; j < 4; j++) acc[i][j] += a[i] * b[j];
        }
        __syncthreads();
    }

    #pragma unroll
    for (int i = 0; i < 4; i++) {
        int r = row0 + ty * 4 + i;
        #pragma unroll
        for (int j = 0; j < 4; j++) {
            int c = n0 + tx * 4 + j;
            if (c < N) C[(size_t)r * ldc + c] = acc[i][j] + bias[c];
        }
    }
}

// ===== GRU gates =====
__global__ __launch_bounds__(256) void k_gates(
    const float* __restrict__ hidden, float* __restrict__ out_newh) {
    int idx = blockIdx.x * 256 + threadIdx.x;
    int b = idx >> 9, j = idx & 511;
    const float* gi = g_gi + b * 3 * HID;
    const float* gh = g_gh + b * 3 * HID;
    float r = sigmoidf_(gi[j] + gh[j]);
    float z = sigmoidf_(gi[HID + j] + gh[HID + j]);
    float n = tanhf(gi[2 * HID + j] + r * gh[2 * HID + j]);
    float h = hidden[idx];
    out_newh[idx] = (1.f - z) * n + z * h;
}

// ===== output softmax =====
__global__ __launch_bounds__(128) void k_out_softmax(
    const float* __restrict__ newh, const float* __restrict__ W_out,
    const float* __restrict__ b_out, float* __restrict__ out_logits) {
    int b = blockIdx.x, tid = threadIdx.x;
    __shared__ float sh[HID];
    __shared__ float se[VOCAB];
    __shared__ float sred[2];
    #pragma unroll
    for (int i = 0; i < 4; i++) sh[tid + i * 128] = newh[b * HID + tid + i * 128];
    __syncthreads();
    if (tid < VOCAB) {
        float acc = b_out[tid];
        #pragma unroll 8
        for (int k = 0; k < HID; k++) acc += sh[k] * W_out[k * VOCAB + tid];
        se[tid] = acc;
    }
    __syncthreads();
    if (tid == 0) {
        float m = se[0];
        for (int i = 1; i < VOCAB; i++) m = fmaxf(m, se[i]);
        sred[0] = m;
    }
    __syncthreads();
    if (tid < VOCAB) se[tid] = __expf(se[tid] - sred[0]);
    __syncthreads();
    if (tid == 0) {
        float s = 0.f;
        for (int i = 0; i < VOCAB; i++) s += se[i];
        sred[1] = 1.f / s;
    }
    __syncthreads();
    if (tid < VOCAB) out_logits[b * VOCAB + tid] = se[tid] * sred[1];
}

// =============================== launcher ===============================
extern "C" void kernel_launch(void* const* d_in, const int* in_sizes, int n_in,
                              void* d_out, int out_size) {
    const float* in_char = (const float*)d_in[0];
    const float* hidden  = (const float*)d_in[1];
    const float* enc     = (const float*)d_in[2];
    const float* W_hp    = (const float*)d_in[3];
    const float* b_hp    = (const float*)d_in[4];
    const float* W_ep    = (const float*)d_in[5];
    const float* b_ep    = (const float*)d_in[6];
    const float* w_v     = (const float*)d_in[7];
    const float* W_cs    = (const float*)d_in[9];
    const float* b_cs    = (const float*)d_in[10];
    const float* emb     = (const float*)d_in[11];
    const float* W_ih    = (const float*)d_in[12];
    const float* b_ih    = (const float*)d_in[13];
    const float* W_hh    = (const float*)d_in[14];
    const float* b_hh    = (const float*)d_in[15];
    const float* W_out   = (const float*)d_in[16];
    const float* b_out   = (const float*)d_in[17];

    float* out = (float*)d_out;
    float* out_logits = out;
    float* out_newh   = out + BATCH * VOCAB;
    float* out_attn   = out + BATCH * VOCAB + BATCH * HID;

    float* p_indec; cudaGetSymbolAddress((void**)&p_indec, g_indec);
    float* p_gi;    cudaGetSymbolAddress((void**)&p_gi, g_gi);
    float* p_gh;    cudaGetSymbolAddress((void**)&p_gh, g_gh);
    float* p_ctx;   cudaGetSymbolAddress((void**)&p_ctx, g_context);
    float* p_hattn; cudaGetSymbolAddress((void**)&p_hattn, g_hidden_attn);

    cudaFuncSetAttribute(k_attn_gemm_mma,
                         cudaFuncAttributeMaxDynamicSharedMemorySize, SMEM_BYTES);

    // attention path
    k_convert_enc<<<(TSEQ * BATCH * HID) / (8 * 256), 256>>>(enc);
    k_transpose_wep<<<dim3(16, 16), 256>>>(W_ep);
    k_gemm64<<<dim3(4, 8), 256>>>(hidden, HID, W_hp, HID, b_hp,
                                  p_hattn, HID, HID, HID);
    k_attn_gemm_mma<<<dim3((TSEQ * BATCH) / 128, 4), 256, SMEM_BYTES>>>(b_ep, w_v);
    k_softmax<<<BATCH, 256>>>(out_attn);
    k_context<<<dim3(BATCH, 4), 256>>>(out_attn);
    k_ctx_combine<<<(BATCH * HID) / 256, 256>>>();

    // decoder tail
    k_argmax_embed<<<BATCH, 64>>>(in_char, emb);
    k_gemm64<<<dim3(4, 4), 256>>>(p_ctx, HID, W_cs, 250, b_cs,
                                  p_indec + EMBED, INDEC_LD, 250, HID);
    k_gemm64<<<dim3(4, 24), 256>>>(p_indec, INDEC_LD, W_ih, 3 * HID, b_ih,
                                   p_gi, 3 * HID, 3 * HID, 300);
    k_gemm64<<<dim3(4, 24), 256>>>(hidden, HID, W_hh, 3 * HID, b_hh,
                                   p_gh, 3 * HID, 3 * HID, HID);
    k_gates<<<(BATCH * HID) / 256, 256>>>(hidden, out_newh);
    k_out_softmax<<<BATCH, 128>>>(out_newh, W_out, b_out, out_logits);
}

// round 17
// speedup vs baseline: 5.5950x; 1.1089x over previous
#include <cuda_runtime.h>
#include <cuda_fp16.h>
#include <math.h>
#include <cstdint>

#define HID 512
#define BATCH 256
#define TSEQ 600
#define VOCAB 83
#define EMBED 50
#define INDEC_LD 304
#define TCHUNK 150

// -------- scratch --------
__device__ float g_hidden_attn[BATCH * HID];
__device__ float g_scores_part[8][BATCH * TSEQ];
__device__ float g_context[BATCH * HID];
__device__ float g_ctx_part[4][BATCH * HID];
__device__ float g_indec[BATCH * INDEC_LD];
__device__ float g_gi[BATCH * 3 * HID];
__device__ float g_gh[BATCH * 3 * HID];
__device__ __half g_encH[(size_t)TSEQ * BATCH * HID];
__device__ __half g_WepH_T[HID * HID];

__device__ __forceinline__ float tanh_fast(float x) {
    float y; asm("tanh.approx.f32 %0, %1;" : "=f"(y) : "f"(x)); return y;
}
__device__ __forceinline__ float sigmoidf_(float x) {
    return 1.0f / (1.0f + __expf(-x));
}
__device__ __forceinline__ void mma_f16(float* c, const uint32_t* a, const uint32_t* b) {
    asm volatile(
        "mma.sync.aligned.m16n8k16.row.col.f32.f16.f16.f32 "
        "{%0,%1,%2,%3}, {%4,%5,%6,%7}, {%8,%9}, {%0,%1,%2,%3};"
        : "+f"(c[0]), "+f"(c[1]), "+f"(c[2]), "+f"(c[3])
        : "r"(a[0]), "r"(a[1]), "r"(a[2]), "r"(a[3]), "r"(b[0]), "r"(b[1]));
}
__device__ __forceinline__ void ldsm_x4(uint32_t* r, uint32_t addr) {
    asm volatile("ldmatrix.sync.aligned.m8n8.x4.shared.b16 {%0,%1,%2,%3}, [%4];"
        : "=r"(r[0]), "=r"(r[1]), "=r"(r[2]), "=r"(r[3]) : "r"(addr));
}
__device__ __forceinline__ void cp_async16(uint32_t dst, const void* src) {
    asm volatile("cp.async.cg.shared.global [%0], [%1], 16;" :: "r"(dst), "l"(src));
}
#define CP_COMMIT() asm volatile("cp.async.commit_group;" ::: "memory")
#define CP_WAIT(n)  asm volatile("cp.async.wait_group %0;" :: "n"(n) : "memory")

// ===== prep: convert enc f32->f16  +  transpose W_ep->f16 =====
#define CONV_BLOCKS ((TSEQ * BATCH * HID) / (8 * 256))
__global__ __launch_bounds__(256) void k_prep(
    const float* __restrict__ enc, const float* __restrict__ W) {
    if (blockIdx.x < CONV_BLOCKS) {
        size_t i8 = ((size_t)blockIdx.x * 256 + threadIdx.x) * 8;
        float4 v0 = *(const float4*)(enc + i8);
        float4 v1 = *(const float4*)(enc + i8 + 4);
        __half2 h[4];
        h[0] = __halves2half2(__float2half_rn(v0.x), __float2half_rn(v0.y));
        h[1] = __halves2half2(__float2half_rn(v0.z), __float2half_rn(v0.w));
        h[2] = __halves2half2(__float2half_rn(v1.x), __float2half_rn(v1.y));
        h[3] = __halves2half2(__float2half_rn(v1.z), __float2half_rn(v1.w));
        const uint32_t* hu = (const uint32_t*)h;
        *(uint2*)(g_encH + i8)     = make_uint2(hu[0], hu[1]);
        *(uint2*)(g_encH + i8 + 4) = make_uint2(hu[2], hu[3]);
    } else {
        __shared__ float t[32][33];
        int bid = blockIdx.x - CONV_BLOCKS;          // 0..255
        int bx = (bid & 15) * 32, by = (bid >> 4) * 32;
        int x = threadIdx.x & 31, y = threadIdx.x >> 5;
        #pragma unroll
        for (int i = 0; i < 32; i += 8)
            t[y + i][x] = W[(size_t)(by + y + i) * HID + bx + x];
        __syncthreads();
        #pragma unroll
        for (int i = 0; i < 32; i += 8)
            g_WepH_T[(size_t)(bx + y + i) * HID + by + x] = __float2half_rn(t[x][y + i]);
    }
}

// ===== K_B: fp16 m16n8k16 GEMM, CTA 128x128, 2 CTAs/SM, grid (4, 1200) =====
#define ASTR 72
#define A_BUF_H (128 * ASTR)
#define B_BUF_H (128 * ASTR)
#define SMEM_BYTES ((A_BUF_H + B_BUF_H) * 2 * 2)

__global__ __launch_bounds__(256, 2) void k_attn_gemm_mma(
    const float* __restrict__ b_ep, const float* __restrict__ w_v) {
    extern __shared__ __half sm[];
    __half* As = sm;
    __half* Bs = sm + 2 * A_BUF_H;

    const int tid = threadIdx.x;
    const int lane = tid & 31, wid = tid >> 5;
    const int warp_m = wid & 3, warp_n = wid >> 2;
    const int row0 = blockIdx.y * 128, n0 = blockIdx.x * 128;  // swapped for L2 A-reuse
    const int qr = lane >> 2, qc = lane & 3;

    const __half* Ag = g_encH + (size_t)row0 * HID;
    const __half* Bg = g_WepH_T + (size_t)n0 * HID;

    const uint32_t sA = (uint32_t)__cvta_generic_to_shared(As);
    const uint32_t sB = (uint32_t)__cvta_generic_to_shared(Bs);

    const int rg = lane & 7;
    const uint32_t aoff = ((warp_m * 32 + ((lane >> 3) & 1) * 8 + rg) * ASTR
                          + ((lane >> 4) & 1) * 8) * 2;
    const uint32_t boff = ((warp_n * 64 + ((lane >> 4) & 1) * 8 + rg) * ASTR
                          + ((lane >> 3) & 1) * 8) * 2;

    const int lr = tid >> 3, lseg = (tid & 7) * 8;
    {
        #pragma unroll
        for (int i = 0; i < 4; i++) {
            int r = lr + i * 32;
            cp_async16(sA + (r * ASTR + lseg) * 2, Ag + (size_t)r * HID + lseg);
            cp_async16(sB + (r * ASTR + lseg) * 2, Bg + (size_t)r * HID + lseg);
        }
        CP_COMMIT();
    }

    float acc[2][8][4];
    #pragma unroll
    for (int m = 0; m < 2; m++)
        #pragma unroll
        for (int j = 0; j < 8; j++)
            #pragma unroll
            for (int i = 0; i < 4; i++) acc[m][j][i] = 0.f;

    for (int c = 0; c < 8; c++) {
        const int buf = c & 1;
        if (c < 7) {
            const int nb = (c + 1) & 1;
            const int k0 = (c + 1) * 64;
            #pragma unroll
            for (int i = 0; i < 4; i++) {
                int r = lr + i * 32;
                cp_async16(sA + (nb * A_BUF_H + r * ASTR + lseg) * 2,
                           Ag + (size_t)r * HID + k0 + lseg);
                cp_async16(sB + (nb * B_BUF_H + r * ASTR + lseg) * 2,
                           Bg + (size_t)r * HID + k0 + lseg);
            }
            CP_COMMIT();
            CP_WAIT(1);
        } else {
            CP_WAIT(0);
        }
        __syncthreads();

        const uint32_t abase = sA + buf * A_BUF_H * 2 + aoff;
        const uint32_t bbase = sB + buf * B_BUF_H * 2 + boff;
        #pragma unroll
        for (int ks = 0; ks < 4; ks++) {
            const int kkb = ks * 16 * 2;
            uint32_t a[2][4];
            #pragma unroll
            for (int m = 0; m < 2; m++)
                ldsm_x4(a[m], abase + m * 16 * ASTR * 2 + kkb);
            uint32_t b[8][2];
            #pragma unroll
            for (int p = 0; p < 4; p++) {
                uint32_t b4[4];
                ldsm_x4(b4, bbase + p * 16 * ASTR * 2 + kkb);
                b[2 * p][0] = b4[0];     b[2 * p][1] = b4[1];
                b[2 * p + 1][0] = b4[2]; b[2 * p + 1][1] = b4[3];
            }
            #pragma unroll
            for (int m = 0; m < 2; m++)
                #pragma unroll
                for (int j = 0; j < 8; j++)
                    mma_f16(acc[m][j], a[m], b[j]);
        }
        __syncthreads();
    }

    float bep_r[16], wv_r[16];
    #pragma unroll
    for (int j = 0; j < 8; j++) {
        int cc = n0 + warp_n * 64 + j * 8 + qc * 2;
        bep_r[j * 2] = b_ep[cc];     bep_r[j * 2 + 1] = b_ep[cc + 1];
        wv_r[j * 2]  = w_v[cc];      wv_r[j * 2 + 1]  = w_v[cc + 1];
    }

    #pragma unroll
    for (int g = 0; g < 4; g++) {
        int m = g >> 1;
        int lrr = warp_m * 32 + m * 16 + (g & 1) * 8 + qr;
        int r = row0 + lrr;
        int bb = r & 255;
        const float* hid = g_hidden_attn + (size_t)bb * HID + n0 + warp_n * 64;
        const int i0 = (g & 1) * 2;
        float p = 0.f;
        #pragma unroll
        for (int j = 0; j < 8; j++) {
            int cl = j * 8 + qc * 2;
            float v0 = acc[m][j][i0]     + bep_r[j * 2]     + hid[cl];
            float v1 = acc[m][j][i0 + 1] + bep_r[j * 2 + 1] + hid[cl + 1];
            p += tanh_fast(v0) * wv_r[j * 2] + tanh_fast(v1) * wv_r[j * 2 + 1];
        }
        p += __shfl_xor_sync(0xffffffffu, p, 1);
        p += __shfl_xor_sync(0xffffffffu, p, 2);
        if (qc == 0) {
            int t = r >> 8;
            g_scores_part[blockIdx.x * 2 + warp_n][bb * TSEQ + t] = p;
        }
    }
}

// ===== fused softmax + context partial; grid (BATCH, 4) =====
__global__ __launch_bounds__(256) void k_ctx_softmax(float* __restrict__ out_attn) {
    int b = blockIdx.x, ch = blockIdx.y, tid = threadIdx.x;
    __shared__ float sw[TSEQ];
    __shared__ float red[256];

    float lm = -1e30f;
    for (int t = tid; t < TSEQ; t += 256) {
        float s = 0.f;
        #pragma unroll
        for (int q = 0; q < 8; q++) s += g_scores_part[q][b * TSEQ + t];
        sw[t] = s;
        lm = fmaxf(lm, s);
    }
    red[tid] = lm;
    __syncthreads();
    for (int off = 128; off > 0; off >>= 1) {
        if (tid < off) red[tid] = fmaxf(red[tid], red[tid + off]);
        __syncthreads();
    }
    float m = red[0];
    __syncthreads();
    float ls = 0.f;
    for (int t = tid; t < TSEQ; t += 256) {
        float e = __expf(sw[t] - m);
        sw[t] = e;
        ls += e;
    }
    red[tid] = ls;
    __syncthreads();
    for (int off = 128; off > 0; off >>= 1) {
        if (tid < off) red[tid] += red[tid + off];
        __syncthreads();
    }
    float inv = 1.f / red[0];
    __syncthreads();
    // normalize full sw; write only this block's attn chunk
    for (int t = tid; t < TSEQ; t += 256) sw[t] *= inv;
    __syncthreads();
    if (tid < TCHUNK)
        out_attn[b * TSEQ + ch * TCHUNK + tid] = sw[ch * TCHUNK + tid];

    float acc0 = 0.f, acc1 = 0.f;
    const __half2* ep = (const __half2*)(g_encH + (size_t)(ch * TCHUNK) * (BATCH * HID)
                                         + (size_t)b * HID) + tid;
    #pragma unroll 4
    for (int t = 0; t < TCHUNK; t++) {
        float w = sw[ch * TCHUNK + t];
        float2 v = __half22float2(ep[(size_t)t * (BATCH * HID / 2)]);
        acc0 += v.x * w;
        acc1 += v.y * w;
    }
    g_ctx_part[ch][b * HID + 2 * tid]     = acc0;
    g_ctx_part[ch][b * HID + 2 * tid + 1] = acc1;
}

__global__ __launch_bounds__(256) void k_ctx_combine() {
    int idx = blockIdx.x * 256 + threadIdx.x;
    g_context[idx] = ((g_ctx_part[0][idx] + g_ctx_part[1][idx])
                    + g_ctx_part[2][idx]) + g_ctx_part[3][idx];
}

// ===== argmax + embed =====
__global__ __launch_bounds__(64) void k_argmax_embed(
    const float* __restrict__ in_char, const float* __restrict__ emb) {
    int b = blockIdx.x, tid = threadIdx.x;
    __shared__ int s_idx;
    if (tid < 32) {
        float bv = -1e30f; int bi = 0;
        for (int i = tid; i < VOCAB; i += 32) {
            float v = in_char[b * VOCAB + i];
            if (v > bv) { bv = v; bi = i; }
        }
        #pragma unroll
        for (int off = 16; off > 0; off >>= 1) {
            float ov = __shfl_down_sync(0xffffffffu, bv, off);
            int   oi = __shfl_down_sync(0xffffffffu, bi, off);
            if (ov > bv || (ov == bv && oi < bi)) { bv = ov; bi = oi; }
        }
        if (tid == 0) s_idx = bi;
    }
    __syncthreads();
    int t1 = s_idx;
    if (tid < EMBED) g_indec[b * INDEC_LD + tid] = emb[t1 * EMBED + tid];
    if (tid >= EMBED && tid < EMBED + 4)
        g_indec[b * INDEC_LD + 300 + (tid - EMBED)] = 0.f;
}

// ===== 64x64 tiled tail GEMM, register-prefetch double-buffer =====
__global__ __launch_bounds__(256) void k_gemm64(
    const float* __restrict__ A, int lda,
    const float* __restrict__ B, int ldb,
    const float* __restrict__ bias,
    float* __restrict__ C, int ldc, int N, int K) {
    __shared__ float As[16][68];
    __shared__ float Bs[16][68];
    const int tid = threadIdx.x;
    const int row0 = blockIdx.x * 64, n0 = blockIdx.y * 64;
    const int tx = tid & 15, ty = tid >> 4;
    const int ar = tid >> 2, aseg = (tid & 3) * 4;
    const int brr = tid >> 4, bn = (tid & 15) * 4;

    float acc[4][4];
    #pragma unroll
    for (int i = 0; i < 4; i++)
        #pragma unroll
        for (int j = 0; j < 4; j++) acc[i][j] = 0.f;

    const int Kpad = (K + 15) & ~15;

    // prefetch k0 = 0
    float4 av = *(const float4*)(A + (size_t)(row0 + ar) * lda + aseg);
    float bv[4];
    #pragma unroll
    for (int i = 0; i < 4; i++) {
        int gk = brr, gn = n0 + bn + i;
        bv[i] = (gk < K && gn < N) ? B[(size_t)gk * ldb + gn] : 0.f;
    }

    for (int k0 = 0; k0 < Kpad; k0 += 16) {
        As[aseg + 0][ar] = av.x;
        As[aseg + 1][ar] = av.y;
        As[aseg + 2][ar] = av.z;
        As[aseg + 3][ar] = av.w;
        #pragma unroll
        for (int i = 0; i < 4; i++) Bs[brr][bn + i] = bv[i];
        __syncthreads();

        if (k0 + 16 < Kpad) {
            av = *(const float4*)(A + (size_t)(row0 + ar) * lda + k0 + 16 + aseg);
            #pragma unroll
            for (int i = 0; i < 4; i++) {
                int gk = k0 + 16 + brr, gn = n0 + bn + i;
                bv[i] = (gk < K && gn < N) ? B[(size_t)gk * ldb + gn] : 0.f;
            }
        }

        #pragma unroll
        for (int k = 0; k < 16; k++) {
            float4 a4 = *(const float4*)&As[k][ty * 4];
            float4 b4 = *(const float4*)&Bs[k][tx * 4];
            float a[4] = {a4.x, a4.y, a4.z, a4.w};
            float b[4] = {b4.x, b4.y, b4.z, b4.w};
            #pragma unroll
            for (int i = 0; i < 4; i++)
                #pragma unroll
                for (int j = 0; j < 4; j++) acc[i][j] += a[i] * b[j];
        }
        __syncthreads();
    }

    #pragma unroll
    for (int i = 0; i < 4; i++) {
        int r = row0 + ty * 4 + i;
        #pragma unroll
        for (int j = 0; j < 4; j++) {
            int c = n0 + tx * 4 + j;
            if (c < N) C[(size_t)r * ldc + c] = acc[i][j] + bias[c];
        }
    }
}

// ===== fused GRU gates + output softmax; grid BATCH, 128 thr =====
__global__ __launch_bounds__(128) void k_gates_out(
    const float* __restrict__ hidden, const float* __restrict__ W_out,
    const float* __restrict__ b_out,
    float* __restrict__ out_logits, float* __restrict__ out_newh) {
    int b = blockIdx.x, tid = threadIdx.x;
    __shared__ float snh[HID];
    __shared__ float se[VOCAB];
    __shared__ float sred[2];

    const float* gi = g_gi + b * 3 * HID;
    const float* gh = g_gh + b * 3 * HID;
    #pragma unroll
    for (int i = 0; i < 4; i++) {
        int j = tid + i * 128;
        float r = sigmoidf_(gi[j] + gh[j]);
        float z = sigmoidf_(gi[HID + j] + gh[HID + j]);
        float n = tanhf(gi[2 * HID + j] + r * gh[2 * HID + j]);
        float h = hidden[b * HID + j];
        float nh = (1.f - z) * n + z * h;
        snh[j] = nh;
        out_newh[b * HID + j] = nh;
    }
    __syncthreads();

    if (tid < VOCAB) {
        float acc = b_out[tid];
        #pragma unroll 8
        for (int k = 0; k < HID; k++) acc += snh[k] * W_out[k * VOCAB + tid];
        se[tid] = acc;
    }
    __syncthreads();
    if (tid == 0) {
        float m = se[0];
        for (int i = 1; i < VOCAB; i++) m = fmaxf(m, se[i]);
        sred[0] = m;
    }
    __syncthreads();
    if (tid < VOCAB) se[tid] = __expf(se[tid] - sred[0]);
    __syncthreads();
    if (tid == 0) {
        float s = 0.f;
        for (int i = 0; i < VOCAB; i++) s += se[i];
        sred[1] = 1.f / s;
    }
    __syncthreads();
    if (tid < VOCAB) out_logits[b * VOCAB + tid] = se[tid] * sred[1];
}

// =============================== launcher ===============================
extern "C" void kernel_launch(void* const* d_in, const int* in_sizes, int n_in,
                              void* d_out, int out_size) {
    const float* in_char = (const float*)d_in[0];
    const float* hidden  = (const float*)d_in[1];
    const float* enc     = (const float*)d_in[2];
    const float* W_hp    = (const float*)d_in[3];
    const float* b_hp    = (const float*)d_in[4];
    const float* W_ep    = (const float*)d_in[5];
    const float* b_ep    = (const float*)d_in[6];
    const float* w_v     = (const float*)d_in[7];
    const float* W_cs    = (const float*)d_in[9];
    const float* b_cs    = (const float*)d_in[10];
    const float* emb     = (const float*)d_in[11];
    const float* W_ih    = (const float*)d_in[12];
    const float* b_ih    = (const float*)d_in[13];
    const float* W_hh    = (const float*)d_in[14];
    const float* b_hh    = (const float*)d_in[15];
    const float* W_out   = (const float*)d_in[16];
    const float* b_out   = (const float*)d_in[17];

    float* out = (float*)d_out;
    float* out_logits = out;
    float* out_newh   = out + BATCH * VOCAB;
    float* out_attn   = out + BATCH * VOCAB + BATCH * HID;

    float* p_indec; cudaGetSymbolAddress((void**)&p_indec, g_indec);
    float* p_gi;    cudaGetSymbolAddress((void**)&p_gi, g_gi);
    float* p_gh;    cudaGetSymbolAddress((void**)&p_gh, g_gh);
    float* p_ctx;   cudaGetSymbolAddress((void**)&p_ctx, g_context);
    float* p_hattn; cudaGetSymbolAddress((void**)&p_hattn, g_hidden_attn);

    cudaFuncSetAttribute(k_attn_gemm_mma,
                         cudaFuncAttributeMaxDynamicSharedMemorySize, SMEM_BYTES);

    // attention path
    k_prep<<<CONV_BLOCKS + 256, 256>>>(enc, W_ep);
    k_gemm64<<<dim3(4, 8), 256>>>(hidden, HID, W_hp, HID, b_hp,
                                  p_hattn, HID, HID, HID);
    k_attn_gemm_mma<<<dim3(4, (TSEQ * BATCH) / 128), 256, SMEM_BYTES>>>(b_ep, w_v);
    k_ctx_softmax<<<dim3(BATCH, 4), 256>>>(out_attn);
    k_ctx_combine<<<(BATCH * HID) / 256, 256>>>();

    // decoder tail
    k_argmax_embed<<<BATCH, 64>>>(in_char, emb);
    k_gemm64<<<dim3(4, 4), 256>>>(p_ctx, HID, W_cs, 250, b_cs,
                                  p_indec + EMBED, INDEC_LD, 250, HID);
    k_gemm64<<<dim3(4, 24), 256>>>(p_indec, INDEC_LD, W_ih, 3 * HID, b_ih,
                                   p_gi, 3 * HID, 3 * HID, 300);
    k_gemm64<<<dim3(4, 24), 256>>>(hidden, HID, W_hh, 3 * HID, b_hh,
                                   p_gh, 3 * HID, 3 * HID, HID);
    k_gates_out<<<BATCH, 128>>>(hidden, W_out, b_out, out_logits, out_newh);
}